// round 6
// baseline (speedup 1.0000x reference)
#include <cuda_runtime.h>
#include <cuda_bf16.h>
#include <cstdint>
#include <cstddef>

#define T_ 512
#define B_ 64
#define EMB_ 256
#define HD_ 256
#define STOP_ 30

// ---------------- device scratch (static: no runtime allocation) ----------
__device__ float g_xw[(size_t)2 * T_ * B_ * 1024];   // [dir][t][b][4H]
__device__ float g_h[(size_t)2 * T_ * B_ * HD_];     // [dir][t][b][H]
__device__ float g_htag[(size_t)T_ * B_ * 32];       // [(t*64+b)][K]
__device__ float g_hbuf[16 * 2 * 8 * HD_];           // [dir*8+G][buf][b][j]
__device__ float g_Wt[512 * 32];                     // W_tag transposed

// =========================================================================
// K1: xW = emb[inp] @ Wih^T + b  (both dirs). 128x128x8 SGEMM, 8x8 micro.
// =========================================================================
__global__ __launch_bounds__(256) void k1_gemm_xw(
    const int* __restrict__ inp, const float* __restrict__ emb,
    const float* __restrict__ Wih_f, const float* __restrict__ b_f,
    const float* __restrict__ Wih_b, const float* __restrict__ b_b)
{
    __shared__ float As[8][128];
    __shared__ float Bs[8][128];
    __shared__ int toks[128];

    const int tid  = threadIdx.x;
    const int row0 = blockIdx.y * 128;
    const int col0 = blockIdx.x * 128;

    if (tid < 128) {
        int r = row0 + tid;                       // r = t*64 + b
        toks[tid] = inp[(r & 63) * T_ + (r >> 6)];
    }
    __syncthreads();

    const int tx = tid & 15;
    const int ty = tid >> 4;
    const int la_r = tid >> 1;
    const int la_k = (tid & 1) * 4;

    const float* asrc = emb + (size_t)toks[la_r] * EMB_ + la_k;
    int gld = col0 + la_r;
    const float* wsrc = (gld < 1024) ? (Wih_f + (size_t)gld * EMB_ + la_k)
                                     : (Wih_b + (size_t)(gld - 1024) * EMB_ + la_k);

    float acc[8][8];
#pragma unroll
    for (int i = 0; i < 8; ++i)
#pragma unroll
        for (int j = 0; j < 8; ++j) acc[i][j] = 0.f;

    for (int k0 = 0; k0 < EMB_; k0 += 8) {
        float4 av = *(const float4*)(asrc + k0);
        float4 bv = *(const float4*)(wsrc + k0);
        __syncthreads();
        As[la_k + 0][la_r] = av.x; As[la_k + 1][la_r] = av.y;
        As[la_k + 2][la_r] = av.z; As[la_k + 3][la_r] = av.w;
        Bs[la_k + 0][la_r] = bv.x; Bs[la_k + 1][la_r] = bv.y;
        Bs[la_k + 2][la_r] = bv.z; Bs[la_k + 3][la_r] = bv.w;
        __syncthreads();
#pragma unroll
        for (int kk = 0; kk < 8; ++kk) {
            float4 a0 = *(const float4*)&As[kk][ty * 8];
            float4 a1 = *(const float4*)&As[kk][ty * 8 + 4];
            float4 b0 = *(const float4*)&Bs[kk][tx * 8];
            float4 b1 = *(const float4*)&Bs[kk][tx * 8 + 4];
            float a[8] = {a0.x, a0.y, a0.z, a0.w, a1.x, a1.y, a1.z, a1.w};
            float b[8] = {b0.x, b0.y, b0.z, b0.w, b1.x, b1.y, b1.z, b1.w};
#pragma unroll
            for (int i = 0; i < 8; ++i)
#pragma unroll
                for (int j = 0; j < 8; ++j)
                    acc[i][j] = fmaf(a[i], b[j], acc[i][j]);
        }
    }

    float bias[8];
#pragma unroll
    for (int j = 0; j < 8; ++j) {
        int g = col0 + tx * 8 + j;
        bias[j] = (g < 1024) ? b_f[g] : b_b[g - 1024];
    }
    const int gbase = col0 + tx * 8;
    const int dir = gbase >> 10;
    const int gi  = gbase & 1023;
#pragma unroll
    for (int i = 0; i < 8; ++i) {
        int r = row0 + ty * 8 + i;
        int t = r >> 6, b = r & 63;
        size_t base = (((size_t)dir * T_ + t) * B_ + b) * 1024 + gi;
        float4 v0 = make_float4(acc[i][0] + bias[0], acc[i][1] + bias[1],
                                acc[i][2] + bias[2], acc[i][3] + bias[3]);
        float4 v1 = make_float4(acc[i][4] + bias[4], acc[i][5] + bias[5],
                                acc[i][6] + bias[6], acc[i][7] + bias[7]);
        *(float4*)&g_xw[base]     = v0;
        *(float4*)&g_xw[base + 4] = v1;
    }
}

// =========================================================================
// K2: BiLSTM recurrence. 128 CTAs, clusters of 8 = (dir, batch-group of 8).
// Rank r owns j in [32r, 32r+32). Whh slice gate-packed in SMEM (128KB).
// Warp w: j_local = 8w + (lane>>2); batch pair bl = 2*(lane&3), bl+1.
// h exchanged via double-buffered global ring + barrier.cluster.
// =========================================================================
#define K2_SMEM (131072 + 8 * 260 * 4)

__device__ __forceinline__ float fsig(float x) { return 1.f / (1.f + __expf(-x)); }

__global__ __launch_bounds__(128, 1) __cluster_dims__(8, 1, 1)
void k2_lstm(const float* __restrict__ Whh_f, const float* __restrict__ Whh_b,
             const int* __restrict__ mask)
{
    extern __shared__ float smem[];
    float* Wv = smem;                   // [k][32 j][4 gates] floats (128KB)
    float* hs = smem + 32768;           // [8 b][260] padded

    const int tid  = threadIdx.x;
    const int rank = blockIdx.x & 7;
    const int cid  = blockIdx.x >> 3;   // 0..15
    const int d    = cid >> 3;          // dir
    const int G    = cid & 7;           // batch group
    const int w    = tid >> 5;
    const int lane = tid & 31;
    const int jq   = lane >> 2;
    const int bp   = lane & 3;
    const int jl   = w * 8 + jq;        // 0..31
    const int jg   = 32 * rank + jl;    // global j
    const int bl0  = 2 * bp;            // local batch
    const int b0   = 8 * G + bl0;
    const int b1   = b0 + 1;

    // load Whh slice into SMEM, gate-packed: Wv[(k*32+j)*4+g] = Whh[g*256+32r+j][k]
    {
        const float* Whh = d ? Whh_b : Whh_f;
        int g  = tid >> 5;               // 4 gates
        int jj = tid & 31;               // 32 rows
        const float* row = Whh + ((size_t)(g * 256 + 32 * rank + jj)) * 256;
        for (int k = 0; k < 256; k += 4) {
            float4 v = *(const float4*)(row + k);
            Wv[((k + 0) * 32 + jj) * 4 + g] = v.x;
            Wv[((k + 1) * 32 + jj) * 4 + g] = v.y;
            Wv[((k + 2) * 32 + jj) * 4 + g] = v.z;
            Wv[((k + 3) * 32 + jj) * 4 + g] = v.w;
        }
    }
    __syncthreads();

    float c0 = 0.f, c1 = 0.f, h0 = 0.f, h1 = 0.f;
    float* hbuf = g_hbuf + (size_t)(d * 8 + G) * 2 * 8 * HD_;
    const float4* Wv4 = (const float4*)Wv;

    const int dt = d ? -1 : 1;
    int t = d ? (T_ - 1) : 0;

    for (int s = 0; s < T_; ++s, t += dt) {
        // prefetch xw gates for this step
        const float* xwp = g_xw + (((size_t)d * T_ + t) * B_) * 1024;
        float xi0 = xwp[(size_t)b0 * 1024 + 0   + jg];
        float xf0 = xwp[(size_t)b0 * 1024 + 256 + jg];
        float xg0 = xwp[(size_t)b0 * 1024 + 512 + jg];
        float xo0 = xwp[(size_t)b0 * 1024 + 768 + jg];
        float xi1 = xwp[(size_t)b1 * 1024 + 0   + jg];
        float xf1 = xwp[(size_t)b1 * 1024 + 256 + jg];
        float xg1 = xwp[(size_t)b1 * 1024 + 512 + jg];
        float xo1 = xwp[(size_t)b1 * 1024 + 768 + jg];

        // refill hs with h_{t-1} for all 8 batches (L2-coherent reads)
        {
            int p = s & 1;
            const float4* src = (const float4*)(hbuf + p * 8 * HD_);
            for (int u = tid; u < 512; u += 128) {
                float4 v;
                if (s == 0) v = make_float4(0.f, 0.f, 0.f, 0.f);
                else        v = __ldcg(src + u);
                int b = u >> 6;
                int j = (u & 63) * 4;
                *(float4*)&hs[b * 260 + j] = v;
            }
        }
        __syncthreads();

        float ai0 = xi0, af0 = xf0, ag0 = xg0, ao0 = xo0;
        float ai1 = xi1, af1 = xf1, ag1 = xg1, ao1 = xo1;
        const float* ha_p = hs + bl0 * 260;
        const float* hb_p = hs + (bl0 + 1) * 260;
#pragma unroll 4
        for (int k = 0; k < 256; ++k) {
            float4 wv = Wv4[k * 32 + jl];   // i,f,g,o
            float ha = ha_p[k];
            float hb = hb_p[k];
            ai0 = fmaf(wv.x, ha, ai0);  ai1 = fmaf(wv.x, hb, ai1);
            af0 = fmaf(wv.y, ha, af0);  af1 = fmaf(wv.y, hb, af1);
            ag0 = fmaf(wv.z, ha, ag0);  ag1 = fmaf(wv.z, hb, ag1);
            ao0 = fmaf(wv.w, ha, ao0);  ao1 = fmaf(wv.w, hb, ao1);
        }

        // cell update + mask
        int m0 = mask[b0 * T_ + t];
        int m1 = mask[b1 * T_ + t];
        {
            float cn = fsig(af0) * c0 + fsig(ai0) * tanhf(ag0);
            float hn = fsig(ao0) * tanhf(cn);
            if (m0) { c0 = cn; h0 = hn; }
            cn = fsig(af1) * c1 + fsig(ai1) * tanhf(ag1);
            hn = fsig(ao1) * tanhf(cn);
            if (m1) { c1 = cn; h1 = hn; }
        }

        // publish h to ring buffer + persistent output
        int q = (s + 1) & 1;
        float* dst = hbuf + q * 8 * HD_;
        dst[bl0 * HD_ + jg - 0] = h0;  // jg includes rank offset; local j index = jg
        dst[(bl0 + 1) * HD_ + jg] = h1;
        float* gh = g_h + (((size_t)d * T_ + t) * B_) * HD_;
        gh[(size_t)b0 * HD_ + jg] = h0;
        gh[(size_t)b1 * HD_ + jg] = h1;

        asm volatile("barrier.cluster.arrive.aligned;" ::: "memory");
        asm volatile("barrier.cluster.wait.aligned;"   ::: "memory");
    }
}

// =========================================================================
// K3: transpose W_tag[32][512] -> g_Wt[512][32]
// =========================================================================
__global__ void k3_wt(const float* __restrict__ W_tag)
{
    int kk = threadIdx.x;  // 512 threads
    for (int k = 0; k < 32; ++k)
        g_Wt[kk * 32 + k] = W_tag[k * 512 + kk];
}

// =========================================================================
// K4: h_tag = [h_f, h_b] @ W_tag^T + b_tag  (unmasked; gated downstream).
// block = 8 rows x 32 tags.
// =========================================================================
__global__ __launch_bounds__(256) void k4_htag(const float* __restrict__ b_tag)
{
    __shared__ float hrow[8][512];
    const int tid = threadIdx.x;
    const int r0 = blockIdx.x * 8;

    for (int u = tid; u < 1024; u += 256) {          // 1024 float4
        int rl = u >> 7;
        int off = (u & 127) * 4;
        int r = r0 + rl;
        int t = r >> 6, b = r & 63;
        const float* src = (off < 256)
            ? &g_h[(((size_t)0 * T_ + t) * B_ + b) * HD_ + off]
            : &g_h[(((size_t)1 * T_ + t) * B_ + b) * HD_ + off - 256];
        *(float4*)&hrow[rl][off] = *(const float4*)src;
    }
    __syncthreads();

    const int rl = tid >> 5;
    const int k  = tid & 31;
    float acc = b_tag[k];
#pragma unroll 8
    for (int kk = 0; kk < 512; ++kk)
        acc = fmaf(hrow[rl][kk], g_Wt[kk * 32 + k], acc);
    g_htag[(size_t)(r0 + rl) * 32 + k] = acc;
}

// =========================================================================
// K5: CRF forward + gold score. One warp per batch, lane = tag.
// =========================================================================
__global__ __launch_bounds__(32) void k5_crf(
    const int* __restrict__ mask, const int* __restrict__ gold,
    const float* __restrict__ trans, float* __restrict__ out)
{
    const int b = blockIdx.x;
    const int k = threadIdx.x;

    float trow[32];
#pragma unroll
    for (int j = 0; j < 32; ++j) trow[j] = trans[k * 32 + j];

    float score = (k == STOP_) ? 0.f : -10000.f;

    for (int t = 0; t < T_; ++t) {
        int m = mask[b * T_ + t];
        float emit = g_htag[((size_t)t * B_ + b) * 32 + k];
        float v[32];
        float mx = -3.4e38f;
#pragma unroll
        for (int j = 0; j < 32; ++j) {
            v[j] = __shfl_sync(0xffffffffu, score, j) + trow[j];
            mx = fmaxf(mx, v[j]);
        }
        float sum = 0.f;
#pragma unroll
        for (int j = 0; j < 32; ++j) sum += __expf(v[j] - mx);
        float sn = emit + mx + __logf(sum);
        score = m ? sn : score;
    }

    // Z = LSE_k(score + trans[STOP][k])
    float zt = score + trans[STOP_ * 32 + k];
    float mx = zt;
#pragma unroll
    for (int o = 16; o; o >>= 1) mx = fmaxf(mx, __shfl_xor_sync(0xffffffffu, mx, o));
    float es = __expf(zt - mx);
#pragma unroll
    for (int o = 16; o; o >>= 1) es += __shfl_xor_sync(0xffffffffu, es, o);
    float Z = mx + __logf(es);

    // gold path score
    float gs = 0.f;
    int len = 0;
    for (int i = k; i < T_; i += 32) {
        int m = mask[b * T_ + i];
        len += m;
        if (i < T_ - 1 && m) {
            int g1 = gold[b * T_ + i + 1];
            int g0 = gold[b * T_ + i];
            gs += g_htag[((size_t)i * B_ + b) * 32 + g1] + trans[g1 * 32 + g0];
        }
    }
#pragma unroll
    for (int o = 16; o; o >>= 1) {
        gs  += __shfl_xor_sync(0xffffffffu, gs, o);
        len += __shfl_xor_sync(0xffffffffu, len, o);
    }
    if (k == 0) {
        int last = gold[b * T_ + len - 1];
        out[b] = Z - (gs + trans[STOP_ * 32 + last]);
    }
}

// =========================================================================
extern "C" void kernel_launch(void* const* d_in, const int* in_sizes, int n_in,
                              void* d_out, int out_size)
{
    const int*   inp   = (const int*)  d_in[0];
    const int*   gold  = (const int*)  d_in[1];
    const int*   mask  = (const int*)  d_in[2];
    const float* emb   = (const float*)d_in[3];
    const float* Wih_f = (const float*)d_in[4];
    const float* Whh_f = (const float*)d_in[5];
    const float* b_f   = (const float*)d_in[6];
    const float* Wih_b = (const float*)d_in[7];
    const float* Whh_b = (const float*)d_in[8];
    const float* b_b   = (const float*)d_in[9];
    const float* W_tag = (const float*)d_in[10];
    const float* b_tag = (const float*)d_in[11];
    const float* trans = (const float*)d_in[12];
    float* out = (float*)d_out;
    (void)in_sizes; (void)n_in; (void)out_size;

    cudaFuncSetAttribute(k2_lstm, cudaFuncAttributeMaxDynamicSharedMemorySize, K2_SMEM);

    k1_gemm_xw<<<dim3(16, 256), 256>>>(inp, emb, Wih_f, b_f, Wih_b, b_b);
    k3_wt<<<1, 512>>>(W_tag);
    k2_lstm<<<128, 128, K2_SMEM>>>(Whh_f, Whh_b, mask);
    k4_htag<<<(T_ * B_) / 8, 256>>>(b_tag);
    k5_crf<<<B_, 32>>>(mask, gold, trans, out);
}

// round 9
// speedup vs baseline: 1.3745x; 1.3745x over previous
#include <cuda_runtime.h>
#include <cuda_bf16.h>
#include <cstdint>
#include <cstddef>

#define T_ 512
#define B_ 64
#define HD_ 256
#define STOP_ 30

// single dynamic-smem symbol (k2 only)
extern __shared__ __align__(16) char dyn_smem[];

// ---------------- device scratch ----------------
__device__ float g_xw[(size_t)2 * T_ * B_ * 1024];   // [dir][t][b][4H]
__device__ float g_h[(size_t)2 * T_ * B_ * HD_];     // [dir][t][b][H]
__device__ float g_htag[(size_t)T_ * B_ * 32];
__device__ float g_hbuf[16 * 2 * 8 * HD_];
__device__ float g_Wt[512 * 32];

// =========================================================================
// K1: xW = emb[inp] @ Wih^T + b  (both dirs). 128x128x8 fp32 SGEMM.
// =========================================================================
__global__ __launch_bounds__(256) void k1_gemm_xw(
    const int* __restrict__ inp, const float* __restrict__ emb,
    const float* __restrict__ Wih_f, const float* __restrict__ b_f,
    const float* __restrict__ Wih_b, const float* __restrict__ b_b)
{
    __shared__ float As[8][128];
    __shared__ float Bs[8][128];
    __shared__ int toks[128];

    const int tid  = threadIdx.x;
    const int row0 = blockIdx.y * 128;
    const int col0 = blockIdx.x * 128;

    if (tid < 128) {
        int r = row0 + tid;                       // r = t*64 + b
        toks[tid] = inp[(r & 63) * T_ + (r >> 6)];
    }
    __syncthreads();

    const int tx = tid & 15;
    const int ty = tid >> 4;
    const int la_r = tid >> 1;
    const int la_k = (tid & 1) * 4;

    const float* asrc = emb + (size_t)toks[la_r] * 256 + la_k;
    int gld = col0 + la_r;
    const float* wsrc = (gld < 1024) ? (Wih_f + (size_t)gld * 256 + la_k)
                                     : (Wih_b + (size_t)(gld - 1024) * 256 + la_k);

    float acc[8][8];
#pragma unroll
    for (int i = 0; i < 8; ++i)
#pragma unroll
        for (int j = 0; j < 8; ++j) acc[i][j] = 0.f;

    for (int k0 = 0; k0 < 256; k0 += 8) {
        float4 av = *(const float4*)(asrc + k0);
        float4 bv = *(const float4*)(wsrc + k0);
        __syncthreads();
        As[la_k + 0][la_r] = av.x; As[la_k + 1][la_r] = av.y;
        As[la_k + 2][la_r] = av.z; As[la_k + 3][la_r] = av.w;
        Bs[la_k + 0][la_r] = bv.x; Bs[la_k + 1][la_r] = bv.y;
        Bs[la_k + 2][la_r] = bv.z; Bs[la_k + 3][la_r] = bv.w;
        __syncthreads();
#pragma unroll
        for (int kk = 0; kk < 8; ++kk) {
            float4 a0 = *(const float4*)&As[kk][ty * 8];
            float4 a1 = *(const float4*)&As[kk][ty * 8 + 4];
            float4 b0 = *(const float4*)&Bs[kk][tx * 8];
            float4 b1 = *(const float4*)&Bs[kk][tx * 8 + 4];
            float a[8] = {a0.x, a0.y, a0.z, a0.w, a1.x, a1.y, a1.z, a1.w};
            float b[8] = {b0.x, b0.y, b0.z, b0.w, b1.x, b1.y, b1.z, b1.w};
#pragma unroll
            for (int i = 0; i < 8; ++i)
#pragma unroll
                for (int j = 0; j < 8; ++j)
                    acc[i][j] = fmaf(a[i], b[j], acc[i][j]);
        }
    }

    float bias[8];
#pragma unroll
    for (int j = 0; j < 8; ++j) {
        int g = col0 + tx * 8 + j;
        bias[j] = (g < 1024) ? b_f[g] : b_b[g - 1024];
    }
    const int gbase = col0 + tx * 8;
    const int dir = gbase >> 10;
    const int gi  = gbase & 1023;
#pragma unroll
    for (int i = 0; i < 8; ++i) {
        int r = row0 + ty * 8 + i;
        int t = r >> 6, b = r & 63;
        size_t base = (((size_t)dir * T_ + t) * B_ + b) * 1024 + gi;
        float4 v0 = make_float4(acc[i][0] + bias[0], acc[i][1] + bias[1],
                                acc[i][2] + bias[2], acc[i][3] + bias[3]);
        float4 v1 = make_float4(acc[i][4] + bias[4], acc[i][5] + bias[5],
                                acc[i][6] + bias[6], acc[i][7] + bias[7]);
        *(float4*)&g_xw[base]     = v0;
        *(float4*)&g_xw[base + 4] = v1;
    }
}

// =========================================================================
// K2: BiLSTM recurrence — split-K over 256 threads (2 warpgroups), xw
// prefetch for next step, mask in SMEM, partial-gate combine via SMEM.
// 128 CTAs, clusters of 8 = (dir, batch-group of 8). Rank owns 32 j's.
// =========================================================================
#define K2_SMEM 148096
__device__ __forceinline__ float fsig(float x) { return 1.f / (1.f + __expf(-x)); }

__global__ __launch_bounds__(256, 1) __cluster_dims__(8, 1, 1)
void k2_lstm(const float* __restrict__ Whh_f, const float* __restrict__ Whh_b,
             const int* __restrict__ mask)
{
    float* smf  = (float*)dyn_smem;
    float* Wv   = smf;                  // 32768 floats [k][32 j][4 gates]
    float* hs   = smf + 32768;          // [8 b][260]
    float* part = smf + 34848;          // [128][9]
    char*  msk  = (char*)(smf + 36000); // [8 b][512]

    const int tid  = threadIdx.x;
    const int rank = blockIdx.x & 7;
    const int cid  = blockIdx.x >> 3;
    const int d    = cid >> 3;
    const int G    = cid & 7;
    const int wt   = tid & 127;
    const int kh   = tid >> 7;          // K-half: 0 -> k[0,128), 1 -> k[128,256)
    const int lane = tid & 31;
    const int jq   = lane >> 2;
    const int bp   = lane & 3;
    const int jl   = ((wt >> 5) * 8) + jq;   // 0..31
    const int jg   = 32 * rank + jl;
    const int bl0  = 2 * bp;
    const int b0   = 8 * G + bl0;
    const int b1   = b0 + 1;

    // Whh slice gate-packed: Wv[(k*32+j)*4+g] = Whh[g*256+32r+j][k]
    if (tid < 128) {
        const float* Whh = d ? Whh_b : Whh_f;
        int g  = tid >> 5;
        int jj = tid & 31;
        const float* row = Whh + (size_t)(g * 256 + 32 * rank + jj) * 256;
        for (int k = 0; k < 256; k += 4) {
            float4 v = *(const float4*)(row + k);
            Wv[((k + 0) * 32 + jj) * 4 + g] = v.x;
            Wv[((k + 1) * 32 + jj) * 4 + g] = v.y;
            Wv[((k + 2) * 32 + jj) * 4 + g] = v.z;
            Wv[((k + 3) * 32 + jj) * 4 + g] = v.w;
        }
    }
    for (int u = tid; u < 4096; u += 256)
        msk[u] = (char)mask[(8 * G + (u >> 9)) * T_ + (u & 511)];
    __syncthreads();

    float c0 = 0.f, c1 = 0.f, h0 = 0.f, h1 = 0.f;
    float* hbuf = g_hbuf + (size_t)(d * 8 + G) * 2 * 8 * HD_;
    const float4* Wv4 = (const float4*)Wv;
    const int dt = d ? -1 : 1;
    int t = d ? (T_ - 1) : 0;

    float px[8];
    if (kh == 0) {
        const float* xa = g_xw + (((size_t)d * T_ + t) * B_ + b0) * 1024 + jg;
        const float* xb = g_xw + (((size_t)d * T_ + t) * B_ + b1) * 1024 + jg;
        px[0] = xa[0]; px[1] = xa[256]; px[2] = xa[512]; px[3] = xa[768];
        px[4] = xb[0]; px[5] = xb[256]; px[6] = xb[512]; px[7] = xb[768];
    }

    for (int s = 0; s < T_; ++s) {
        // refill hs from ring (peers' h from previous step)
        {
            const float4* src = (const float4*)(hbuf + (s & 1) * 2048);
            for (int u = tid; u < 512; u += 256) {
                float4 v = (s == 0) ? make_float4(0.f, 0.f, 0.f, 0.f) : __ldcg(src + u);
                *(float4*)&hs[(u >> 6) * 260 + (u & 63) * 4] = v;
            }
        }
        __syncthreads();

        float ai0, af0, ag0, ao0, ai1, af1, ag1, ao1;
        if (kh == 0) {
            ai0 = px[0]; af0 = px[1]; ag0 = px[2]; ao0 = px[3];
            ai1 = px[4]; af1 = px[5]; ag1 = px[6]; ao1 = px[7];
            if (s + 1 < T_) {      // prefetch next step's xw under the FMA loop
                int tn = t + dt;
                const float* xa = g_xw + (((size_t)d * T_ + tn) * B_ + b0) * 1024 + jg;
                const float* xb = g_xw + (((size_t)d * T_ + tn) * B_ + b1) * 1024 + jg;
                px[0] = xa[0]; px[1] = xa[256]; px[2] = xa[512]; px[3] = xa[768];
                px[4] = xb[0]; px[5] = xb[256]; px[6] = xb[512]; px[7] = xb[768];
            }
        } else {
            ai0 = af0 = ag0 = ao0 = ai1 = af1 = ag1 = ao1 = 0.f;
        }

        const float* ha_p = hs + bl0 * 260 + kh * 128;
        const float* hb_p = ha_p + 260;
        const int kbase = kh * 128;
#pragma unroll 4
        for (int k = 0; k < 128; ++k) {
            float4 wv = Wv4[(kbase + k) * 32 + jl];
            float ha = ha_p[k];
            float hb = hb_p[k];
            ai0 = fmaf(wv.x, ha, ai0);  ai1 = fmaf(wv.x, hb, ai1);
            af0 = fmaf(wv.y, ha, af0);  af1 = fmaf(wv.y, hb, af1);
            ag0 = fmaf(wv.z, ha, ag0);  ag1 = fmaf(wv.z, hb, ag1);
            ao0 = fmaf(wv.w, ha, ao0);  ao1 = fmaf(wv.w, hb, ao1);
        }

        if (kh == 1) {
            float* pp = part + wt * 9;
            pp[0] = ai0; pp[1] = af0; pp[2] = ag0; pp[3] = ao0;
            pp[4] = ai1; pp[5] = af1; pp[6] = ag1; pp[7] = ao1;
        }
        __syncthreads();
        if (kh == 0) {
            const float* pp = part + wt * 9;
            ai0 += pp[0]; af0 += pp[1]; ag0 += pp[2]; ao0 += pp[3];
            ai1 += pp[4]; af1 += pp[5]; ag1 += pp[6]; ao1 += pp[7];

            int m0 = msk[bl0 * 512 + t];
            int m1 = msk[(bl0 + 1) * 512 + t];
            float cn = fsig(af0) * c0 + fsig(ai0) * tanhf(ag0);
            float hn = fsig(ao0) * tanhf(cn);
            if (m0) { c0 = cn; h0 = hn; }
            cn = fsig(af1) * c1 + fsig(ai1) * tanhf(ag1);
            hn = fsig(ao1) * tanhf(cn);
            if (m1) { c1 = cn; h1 = hn; }

            float* dst = hbuf + ((s + 1) & 1) * 2048;
            dst[bl0 * HD_ + jg]       = h0;
            dst[(bl0 + 1) * HD_ + jg] = h1;
            float* gh = g_h + (((size_t)d * T_ + t) * B_) * HD_;
            gh[(size_t)b0 * HD_ + jg] = h0;
            gh[(size_t)b1 * HD_ + jg] = h1;
        }
        asm volatile("barrier.cluster.arrive.aligned;" ::: "memory");
        asm volatile("barrier.cluster.wait.aligned;"   ::: "memory");
        t += dt;
    }
}

// =========================================================================
// K3: W_tag transpose
// =========================================================================
__global__ void k3_wt(const float* __restrict__ W_tag)
{
    int kk = threadIdx.x;
    for (int k = 0; k < 32; ++k)
        g_Wt[kk * 32 + k] = W_tag[k * 512 + kk];
}

// =========================================================================
// K4: h_tag = [h_f,h_b] @ W_tag^T + b_tag
// =========================================================================
__global__ __launch_bounds__(256) void k4_htag(const float* __restrict__ b_tag)
{
    __shared__ float hrow[8][512];
    const int tid = threadIdx.x;
    const int r0 = blockIdx.x * 8;

    for (int u = tid; u < 1024; u += 256) {
        int rl = u >> 7;
        int off = (u & 127) * 4;
        int r = r0 + rl;
        int t = r >> 6, b = r & 63;
        const float* src = (off < 256)
            ? &g_h[(((size_t)0 * T_ + t) * B_ + b) * HD_ + off]
            : &g_h[(((size_t)1 * T_ + t) * B_ + b) * HD_ + off - 256];
        *(float4*)&hrow[rl][off] = *(const float4*)src;
    }
    __syncthreads();

    const int rl = tid >> 5;
    const int k  = tid & 31;
    float acc = b_tag[k];
#pragma unroll 8
    for (int kk = 0; kk < 512; ++kk)
        acc = fmaf(hrow[rl][kk], g_Wt[kk * 32 + k], acc);
    g_htag[(size_t)(r0 + rl) * 32 + k] = acc;
}

// =========================================================================
// K5: CRF forward + gold score. Warp per batch, lane = tag.
// Tree reductions, ballot-packed mask, emit prefetch.
// =========================================================================
__global__ __launch_bounds__(32) void k5_crf(
    const int* __restrict__ mask, const int* __restrict__ gold,
    const float* __restrict__ trans, float* __restrict__ out)
{
    __shared__ unsigned mw[16];
    const int b = blockIdx.x;
    const int k = threadIdx.x;

    float trow[32];
#pragma unroll
    for (int j = 0; j < 32; ++j) trow[j] = trans[k * 32 + j];

    for (int blk = 0; blk < 16; ++blk) {
        int bit = mask[b * T_ + blk * 32 + k];
        unsigned wword = __ballot_sync(0xffffffffu, bit != 0);
        if (k == 0) mw[blk] = wword;
    }
    __syncwarp();

    float score = (k == STOP_) ? 0.f : -10000.f;
    float emit = g_htag[((size_t)0 * B_ + b) * 32 + k];

    for (int t = 0; t < T_; ++t) {
        int tn = (t + 1 < T_) ? t + 1 : t;
        float emit_n = g_htag[((size_t)tn * B_ + b) * 32 + k];
        int m = (mw[t >> 5] >> (t & 31)) & 1;

        float v[32];
#pragma unroll
        for (int j = 0; j < 32; ++j)
            v[j] = __shfl_sync(0xffffffffu, score, j) + trow[j];

        float m16[16], m8[8], m4[4], m2[2];
#pragma unroll
        for (int j = 0; j < 16; ++j) m16[j] = fmaxf(v[j], v[j + 16]);
#pragma unroll
        for (int j = 0; j < 8; ++j)  m8[j] = fmaxf(m16[j], m16[j + 8]);
#pragma unroll
        for (int j = 0; j < 4; ++j)  m4[j] = fmaxf(m8[j], m8[j + 4]);
        m2[0] = fmaxf(m4[0], m4[2]); m2[1] = fmaxf(m4[1], m4[3]);
        float mx = fmaxf(m2[0], m2[1]);

        float e[32];
#pragma unroll
        for (int j = 0; j < 32; ++j) e[j] = __expf(v[j] - mx);
        float s16[16], s8[8], s4[4], s2[2];
#pragma unroll
        for (int j = 0; j < 16; ++j) s16[j] = e[j] + e[j + 16];
#pragma unroll
        for (int j = 0; j < 8; ++j)  s8[j] = s16[j] + s16[j + 8];
#pragma unroll
        for (int j = 0; j < 4; ++j)  s4[j] = s8[j] + s8[j + 4];
        s2[0] = s4[0] + s4[2]; s2[1] = s4[1] + s4[3];
        float sum = s2[0] + s2[1];

        float sn = emit + mx + __logf(sum);
        score = m ? sn : score;
        emit = emit_n;
    }

    float zt = score + trans[STOP_ * 32 + k];
    float mx = zt;
#pragma unroll
    for (int o = 16; o; o >>= 1) mx = fmaxf(mx, __shfl_xor_sync(0xffffffffu, mx, o));
    float es = __expf(zt - mx);
#pragma unroll
    for (int o = 16; o; o >>= 1) es += __shfl_xor_sync(0xffffffffu, es, o);
    float Z = mx + __logf(es);

    float gs = 0.f;
    int len = 0;
    for (int i = k; i < T_; i += 32) {
        int m = mask[b * T_ + i];
        len += m;
        if (i < T_ - 1 && m) {
            int g1 = gold[b * T_ + i + 1];
            int g0 = gold[b * T_ + i];
            gs += g_htag[((size_t)i * B_ + b) * 32 + g1] + trans[g1 * 32 + g0];
        }
    }
#pragma unroll
    for (int o = 16; o; o >>= 1) {
        gs  += __shfl_xor_sync(0xffffffffu, gs, o);
        len += __shfl_xor_sync(0xffffffffu, len, o);
    }
    if (k == 0) {
        int last = gold[b * T_ + len - 1];
        out[b] = Z - (gs + trans[STOP_ * 32 + last]);
    }
}

// =========================================================================
extern "C" void kernel_launch(void* const* d_in, const int* in_sizes, int n_in,
                              void* d_out, int out_size)
{
    const int*   inp   = (const int*)  d_in[0];
    const int*   gold  = (const int*)  d_in[1];
    const int*   mask  = (const int*)  d_in[2];
    const float* emb   = (const float*)d_in[3];
    const float* Wih_f = (const float*)d_in[4];
    const float* Whh_f = (const float*)d_in[5];
    const float* b_f   = (const float*)d_in[6];
    const float* Wih_b = (const float*)d_in[7];
    const float* Whh_b = (const float*)d_in[8];
    const float* b_b   = (const float*)d_in[9];
    const float* W_tag = (const float*)d_in[10];
    const float* b_tag = (const float*)d_in[11];
    const float* trans = (const float*)d_in[12];
    float* out = (float*)d_out;
    (void)in_sizes; (void)n_in; (void)out_size;

    cudaFuncSetAttribute(k2_lstm, cudaFuncAttributeMaxDynamicSharedMemorySize, K2_SMEM);

    k1_gemm_xw<<<dim3(16, 256), 256>>>(inp, emb, Wih_f, b_f, Wih_b, b_b);
    k3_wt<<<1, 512>>>(W_tag);
    k2_lstm<<<128, 256, K2_SMEM>>>(Whh_f, Whh_b, mask);
    k4_htag<<<(T_ * B_) / 8, 256>>>(b_tag);
    k5_crf<<<B_, 32>>>(mask, gold, trans, out);
}

// round 10
// speedup vs baseline: 1.5002x; 1.0915x over previous
#include <cuda_runtime.h>
#include <cuda_bf16.h>
#include <cstdint>
#include <cstddef>

#define T_ 512
#define B_ 64
#define HD_ 256
#define STOP_ 30

// single dynamic-smem symbol
extern __shared__ __align__(16) char dyn_smem[];

// ---------------- device scratch ----------------
__device__ float g_xw[(size_t)2 * T_ * B_ * 1024];   // [dir][t][b][4H]
__device__ float g_h[(size_t)2 * T_ * B_ * HD_];     // [dir][t][b][H]
__device__ float g_htag[(size_t)T_ * B_ * 32];
__device__ float g_hbuf[16 * 2 * 8 * HD_];
__device__ float g_Wt[512 * 32];
__device__ __nv_bfloat16 g_ahi[(size_t)32768 * 256];
__device__ __nv_bfloat16 g_alo[(size_t)32768 * 256];
__device__ __nv_bfloat16 g_bhi[(size_t)2048 * 256];
__device__ __nv_bfloat16 g_blo[(size_t)2048 * 256];

// =========================================================================
// K0: gather emb rows + split-convert A and B to bf16 hi/lo.
// A row r = t*64+b -> emb[inp[b][t]]. B row = Wih gate row (both dirs).
// =========================================================================
__global__ __launch_bounds__(256) void k0_conv(
    const int* __restrict__ inp, const float* __restrict__ emb,
    const float* __restrict__ Wih_f, const float* __restrict__ Wih_b)
{
    size_t u = (size_t)blockIdx.x * 256 + threadIdx.x;   // float4 index
    const float* src;
    __nv_bfloat16 *dhi, *dlo;
    size_t off;
    if (u < 2097152) {                     // A: 32768 rows * 64 float4
        int r = (int)(u >> 6);
        int q = (int)(u & 63);
        int tok = inp[(r & 63) * T_ + (r >> 6)];
        src = emb + (size_t)tok * 256 + q * 4;
        off = (size_t)r * 256 + q * 4;
        dhi = g_ahi; dlo = g_alo;
    } else {                               // B: 2048 rows * 64 float4
        size_t v = u - 2097152;
        if (v >= 131072) return;
        int r = (int)(v >> 6);
        int q = (int)(v & 63);
        src = (r < 1024 ? Wih_f + (size_t)r * 256
                        : Wih_b + (size_t)(r - 1024) * 256) + q * 4;
        off = (size_t)r * 256 + q * 4;
        dhi = g_bhi; dlo = g_blo;
    }
    float4 a = *(const float4*)src;
    __nv_bfloat162 h0 = __floats2bfloat162_rn(a.x, a.y);
    __nv_bfloat162 h1 = __floats2bfloat162_rn(a.z, a.w);
    __nv_bfloat162 l0 = __floats2bfloat162_rn(a.x - __bfloat162float(h0.x),
                                              a.y - __bfloat162float(h0.y));
    __nv_bfloat162 l1 = __floats2bfloat162_rn(a.z - __bfloat162float(h1.x),
                                              a.w - __bfloat162float(h1.y));
    *(uint2*)(dhi + off) = make_uint2(*(uint32_t*)&h0, *(uint32_t*)&h1);
    *(uint2*)(dlo + off) = make_uint2(*(uint32_t*)&l0, *(uint32_t*)&l1);
}

// =========================================================================
// K1: xW = A @ B^T + bias via mma.sync bf16 split (3 passes, fp32 accum).
// CTA tile 128x128, K chunks of 64, 8 warps in 2(m) x 4(n), warp m64n32.
// =========================================================================
__device__ __forceinline__ uint32_t smem_u32(const void* p) {
    uint32_t a;
    asm("{ .reg .u64 t; cvta.to.shared.u64 t, %1; cvt.u32.u64 %0, t; }" : "=r"(a) : "l"(p));
    return a;
}
#define LDSM_X4(r, addr) \
    asm volatile("ldmatrix.sync.aligned.m8n8.x4.shared.b16 {%0,%1,%2,%3}, [%4];" \
        : "=r"((r)[0]), "=r"((r)[1]), "=r"((r)[2]), "=r"((r)[3]) : "r"(addr))
#define LDSM_X2(r, addr) \
    asm volatile("ldmatrix.sync.aligned.m8n8.x2.shared.b16 {%0,%1}, [%2];" \
        : "=r"((r)[0]), "=r"((r)[1]) : "r"(addr))
__device__ __forceinline__ void mma16816(float* c, const uint32_t* a, const uint32_t* b) {
    asm volatile("mma.sync.aligned.m16n8k16.row.col.f32.bf16.bf16.f32 "
        "{%0,%1,%2,%3}, {%4,%5,%6,%7}, {%8,%9}, {%0,%1,%2,%3};"
        : "+f"(c[0]), "+f"(c[1]), "+f"(c[2]), "+f"(c[3])
        : "r"(a[0]), "r"(a[1]), "r"(a[2]), "r"(a[3]), "r"(b[0]), "r"(b[1]));
}

#define K1_STR  72                          // bf16 elems per smem row
#define K1_AHI  0
#define K1_ALO  (128 * K1_STR)
#define K1_BHI  (2 * 128 * K1_STR)
#define K1_BLO  (3 * 128 * K1_STR)
#define K1_BIAS_B (4 * 128 * K1_STR * 2)    // byte offset of bias
#define K1_SMEM (K1_BIAS_B + 512 + 128)

__global__ __launch_bounds__(256, 2) void k1_mma(
    const float* __restrict__ b_f, const float* __restrict__ b_b)
{
    __nv_bfloat16* smb = (__nv_bfloat16*)dyn_smem;
    float* sbias = (float*)(dyn_smem + K1_BIAS_B);
    const uint32_t sA = smem_u32(smb);
    const int tid = threadIdx.x;
    const int wid = tid >> 5, lane = tid & 31;
    const int row0 = blockIdx.y * 128;
    const int col0 = blockIdx.x * 128;
    const int dir = col0 >> 10, gi0 = col0 & 1023;
    const int wm = wid >> 2, wn = wid & 3;

    if (tid < 128) {
        int g = col0 + tid;
        sbias[tid] = (g < 1024) ? b_f[g] : b_b[g - 1024];
    }

    float acc[4][4][4];
#pragma unroll
    for (int i = 0; i < 4; ++i)
#pragma unroll
        for (int j = 0; j < 4; ++j)
#pragma unroll
            for (int e = 0; e < 4; ++e) acc[i][j][e] = 0.f;

    for (int kc = 0; kc < 4; ++kc) {
        __syncthreads();
        {   // stage chunk: 4 matrices, 16B per thread per matrix per i
            int r  = tid >> 1;
            int g2 = (tid & 1) * 4;
            size_t abase = (size_t)(row0 + r) * 256 + kc * 64 + g2 * 8;
            size_t bbase = (size_t)(col0 + r) * 256 + kc * 64 + g2 * 8;
            int so = r * K1_STR + g2 * 8;
#pragma unroll
            for (int i = 0; i < 4; ++i) {
                *(uint4*)(smb + K1_AHI + so + i * 8) = *(const uint4*)(g_ahi + abase + i * 8);
                *(uint4*)(smb + K1_ALO + so + i * 8) = *(const uint4*)(g_alo + abase + i * 8);
                *(uint4*)(smb + K1_BHI + so + i * 8) = *(const uint4*)(g_bhi + bbase + i * 8);
                *(uint4*)(smb + K1_BLO + so + i * 8) = *(const uint4*)(g_blo + bbase + i * 8);
            }
        }
        __syncthreads();

#pragma unroll
        for (int ks = 0; ks < 4; ++ks) {
            uint32_t bh[4][2], bl[4][2];
#pragma unroll
            for (int nf = 0; nf < 4; ++nf) {
                int nrow = wn * 32 + nf * 8 + (lane & 7);
                int kof  = ks * 16 + ((lane >> 3) & 1) * 8;
                LDSM_X2(bh[nf], sA + (uint32_t)(K1_BHI + nrow * K1_STR + kof) * 2);
                LDSM_X2(bl[nf], sA + (uint32_t)(K1_BLO + nrow * K1_STR + kof) * 2);
            }
            uint32_t af[4][4];
            {
                int mrow = wm * 64 + (lane & 15);
                int kof  = ks * 16 + (lane >> 4) * 8;
#pragma unroll
                for (int mf = 0; mf < 4; ++mf)
                    LDSM_X4(af[mf], sA + (uint32_t)(K1_AHI + (mrow + mf * 16) * K1_STR + kof) * 2);
#pragma unroll
                for (int mf = 0; mf < 4; ++mf)
#pragma unroll
                    for (int nf = 0; nf < 4; ++nf) {
                        mma16816(acc[mf][nf], af[mf], bh[nf]);
                        mma16816(acc[mf][nf], af[mf], bl[nf]);
                    }
#pragma unroll
                for (int mf = 0; mf < 4; ++mf)
                    LDSM_X4(af[mf], sA + (uint32_t)(K1_ALO + (mrow + mf * 16) * K1_STR + kof) * 2);
#pragma unroll
                for (int mf = 0; mf < 4; ++mf)
#pragma unroll
                    for (int nf = 0; nf < 4; ++nf)
                        mma16816(acc[mf][nf], af[mf], bh[nf]);
            }
        }
    }

    // epilogue: D frag (c0,c1)=row g cols 2t,2t+1 ; (c2,c3)=row g+8
    const int gq = lane >> 2, tq = lane & 3;
#pragma unroll
    for (int mf = 0; mf < 4; ++mf)
#pragma unroll
        for (int i2 = 0; i2 < 2; ++i2) {
            int m = wm * 64 + mf * 16 + gq + i2 * 8;
            int r = row0 + m;
            int t = r >> 6, b = r & 63;
            float* dst = g_xw + (((size_t)dir * T_ + t) * B_ + b) * 1024 + gi0;
#pragma unroll
            for (int nf = 0; nf < 4; ++nf) {
                int n = wn * 32 + nf * 8 + tq * 2;
                float2 v;
                v.x = acc[mf][nf][i2 * 2 + 0] + sbias[n];
                v.y = acc[mf][nf][i2 * 2 + 1] + sbias[n + 1];
                *(float2*)(dst + n) = v;
            }
        }
}

// =========================================================================
// K2: BiLSTM recurrence (unchanged from R9 passing version).
// =========================================================================
#define K2_SMEM 148096
__device__ __forceinline__ float fsig(float x) { return 1.f / (1.f + __expf(-x)); }

__global__ __launch_bounds__(256, 1) __cluster_dims__(8, 1, 1)
void k2_lstm(const float* __restrict__ Whh_f, const float* __restrict__ Whh_b,
             const int* __restrict__ mask)
{
    float* smf  = (float*)dyn_smem;
    float* Wv   = smf;                  // 32768 floats [k][32 j][4 gates]
    float* hs   = smf + 32768;          // [8 b][260]
    float* part = smf + 34848;          // [128][9]
    char*  msk  = (char*)(smf + 36000); // [8 b][512]

    const int tid  = threadIdx.x;
    const int rank = blockIdx.x & 7;
    const int cid  = blockIdx.x >> 3;
    const int d    = cid >> 3;
    const int G    = cid & 7;
    const int wt   = tid & 127;
    const int kh   = tid >> 7;
    const int lane = tid & 31;
    const int jq   = lane >> 2;
    const int bp   = lane & 3;
    const int jl   = ((wt >> 5) * 8) + jq;
    const int jg   = 32 * rank + jl;
    const int bl0  = 2 * bp;
    const int b0   = 8 * G + bl0;
    const int b1   = b0 + 1;

    if (tid < 128) {
        const float* Whh = d ? Whh_b : Whh_f;
        int g  = tid >> 5;
        int jj = tid & 31;
        const float* row = Whh + (size_t)(g * 256 + 32 * rank + jj) * 256;
        for (int k = 0; k < 256; k += 4) {
            float4 v = *(const float4*)(row + k);
            Wv[((k + 0) * 32 + jj) * 4 + g] = v.x;
            Wv[((k + 1) * 32 + jj) * 4 + g] = v.y;
            Wv[((k + 2) * 32 + jj) * 4 + g] = v.z;
            Wv[((k + 3) * 32 + jj) * 4 + g] = v.w;
        }
    }
    for (int u = tid; u < 4096; u += 256)
        msk[u] = (char)mask[(8 * G + (u >> 9)) * T_ + (u & 511)];
    __syncthreads();

    float c0 = 0.f, c1 = 0.f, h0 = 0.f, h1 = 0.f;
    float* hbuf = g_hbuf + (size_t)(d * 8 + G) * 2 * 8 * HD_;
    const float4* Wv4 = (const float4*)Wv;
    const int dt = d ? -1 : 1;
    int t = d ? (T_ - 1) : 0;

    float px[8];
    if (kh == 0) {
        const float* xa = g_xw + (((size_t)d * T_ + t) * B_ + b0) * 1024 + jg;
        const float* xb = g_xw + (((size_t)d * T_ + t) * B_ + b1) * 1024 + jg;
        px[0] = xa[0]; px[1] = xa[256]; px[2] = xa[512]; px[3] = xa[768];
        px[4] = xb[0]; px[5] = xb[256]; px[6] = xb[512]; px[7] = xb[768];
    }

    for (int s = 0; s < T_; ++s) {
        {
            const float4* src = (const float4*)(hbuf + (s & 1) * 2048);
            for (int u = tid; u < 512; u += 256) {
                float4 v = (s == 0) ? make_float4(0.f, 0.f, 0.f, 0.f) : __ldcg(src + u);
                *(float4*)&hs[(u >> 6) * 260 + (u & 63) * 4] = v;
            }
        }
        __syncthreads();

        float ai0, af0, ag0, ao0, ai1, af1, ag1, ao1;
        if (kh == 0) {
            ai0 = px[0]; af0 = px[1]; ag0 = px[2]; ao0 = px[3];
            ai1 = px[4]; af1 = px[5]; ag1 = px[6]; ao1 = px[7];
            if (s + 1 < T_) {
                int tn = t + dt;
                const float* xa = g_xw + (((size_t)d * T_ + tn) * B_ + b0) * 1024 + jg;
                const float* xb = g_xw + (((size_t)d * T_ + tn) * B_ + b1) * 1024 + jg;
                px[0] = xa[0]; px[1] = xa[256]; px[2] = xa[512]; px[3] = xa[768];
                px[4] = xb[0]; px[5] = xb[256]; px[6] = xb[512]; px[7] = xb[768];
            }
        } else {
            ai0 = af0 = ag0 = ao0 = ai1 = af1 = ag1 = ao1 = 0.f;
        }

        const float* ha_p = hs + bl0 * 260 + kh * 128;
        const float* hb_p = ha_p + 260;
        const int kbase = kh * 128;
#pragma unroll 4
        for (int k = 0; k < 128; ++k) {
            float4 wv = Wv4[(kbase + k) * 32 + jl];
            float ha = ha_p[k];
            float hb = hb_p[k];
            ai0 = fmaf(wv.x, ha, ai0);  ai1 = fmaf(wv.x, hb, ai1);
            af0 = fmaf(wv.y, ha, af0);  af1 = fmaf(wv.y, hb, af1);
            ag0 = fmaf(wv.z, ha, ag0);  ag1 = fmaf(wv.z, hb, ag1);
            ao0 = fmaf(wv.w, ha, ao0);  ao1 = fmaf(wv.w, hb, ao1);
        }

        if (kh == 1) {
            float* pp = part + wt * 9;
            pp[0] = ai0; pp[1] = af0; pp[2] = ag0; pp[3] = ao0;
            pp[4] = ai1; pp[5] = af1; pp[6] = ag1; pp[7] = ao1;
        }
        __syncthreads();
        if (kh == 0) {
            const float* pp = part + wt * 9;
            ai0 += pp[0]; af0 += pp[1]; ag0 += pp[2]; ao0 += pp[3];
            ai1 += pp[4]; af1 += pp[5]; ag1 += pp[6]; ao1 += pp[7];

            int m0 = msk[bl0 * 512 + t];
            int m1 = msk[(bl0 + 1) * 512 + t];
            float cn = fsig(af0) * c0 + fsig(ai0) * tanhf(ag0);
            float hn = fsig(ao0) * tanhf(cn);
            if (m0) { c0 = cn; h0 = hn; }
            cn = fsig(af1) * c1 + fsig(ai1) * tanhf(ag1);
            hn = fsig(ao1) * tanhf(cn);
            if (m1) { c1 = cn; h1 = hn; }

            float* dst = hbuf + ((s + 1) & 1) * 2048;
            dst[bl0 * HD_ + jg]       = h0;
            dst[(bl0 + 1) * HD_ + jg] = h1;
            float* gh = g_h + (((size_t)d * T_ + t) * B_) * HD_;
            gh[(size_t)b0 * HD_ + jg] = h0;
            gh[(size_t)b1 * HD_ + jg] = h1;
        }
        asm volatile("barrier.cluster.arrive.aligned;" ::: "memory");
        asm volatile("barrier.cluster.wait.aligned;"   ::: "memory");
        t += dt;
    }
}

// =========================================================================
// K3: W_tag transpose
// =========================================================================
__global__ void k3_wt(const float* __restrict__ W_tag)
{
    int kk = threadIdx.x;
    for (int k = 0; k < 32; ++k)
        g_Wt[kk * 32 + k] = W_tag[k * 512 + kk];
}

// =========================================================================
// K4: h_tag = [h_f,h_b] @ W_tag^T + b_tag
// =========================================================================
__global__ __launch_bounds__(256) void k4_htag(const float* __restrict__ b_tag)
{
    __shared__ float hrow[8][512];
    const int tid = threadIdx.x;
    const int r0 = blockIdx.x * 8;

    for (int u = tid; u < 1024; u += 256) {
        int rl = u >> 7;
        int off = (u & 127) * 4;
        int r = r0 + rl;
        int t = r >> 6, b = r & 63;
        const float* src = (off < 256)
            ? &g_h[(((size_t)0 * T_ + t) * B_ + b) * HD_ + off]
            : &g_h[(((size_t)1 * T_ + t) * B_ + b) * HD_ + off - 256];
        *(float4*)&hrow[rl][off] = *(const float4*)src;
    }
    __syncthreads();

    const int rl = tid >> 5;
    const int k  = tid & 31;
    float acc = b_tag[k];
#pragma unroll 8
    for (int kk = 0; kk < 512; ++kk)
        acc = fmaf(hrow[rl][kk], g_Wt[kk * 32 + k], acc);
    g_htag[(size_t)(r0 + rl) * 32 + k] = acc;
}

// =========================================================================
// K5: CRF forward + gold score (unchanged from R9).
// =========================================================================
__global__ __launch_bounds__(32) void k5_crf(
    const int* __restrict__ mask, const int* __restrict__ gold,
    const float* __restrict__ trans, float* __restrict__ out)
{
    __shared__ unsigned mw[16];
    const int b = blockIdx.x;
    const int k = threadIdx.x;

    float trow[32];
#pragma unroll
    for (int j = 0; j < 32; ++j) trow[j] = trans[k * 32 + j];

    for (int blk = 0; blk < 16; ++blk) {
        int bit = mask[b * T_ + blk * 32 + k];
        unsigned wword = __ballot_sync(0xffffffffu, bit != 0);
        if (k == 0) mw[blk] = wword;
    }
    __syncwarp();

    float score = (k == STOP_) ? 0.f : -10000.f;
    float emit = g_htag[((size_t)0 * B_ + b) * 32 + k];

    for (int t = 0; t < T_; ++t) {
        int tn = (t + 1 < T_) ? t + 1 : t;
        float emit_n = g_htag[((size_t)tn * B_ + b) * 32 + k];
        int m = (mw[t >> 5] >> (t & 31)) & 1;

        float v[32];
#pragma unroll
        for (int j = 0; j < 32; ++j)
            v[j] = __shfl_sync(0xffffffffu, score, j) + trow[j];

        float m16[16], m8[8], m4[4], m2[2];
#pragma unroll
        for (int j = 0; j < 16; ++j) m16[j] = fmaxf(v[j], v[j + 16]);
#pragma unroll
        for (int j = 0; j < 8; ++j)  m8[j] = fmaxf(m16[j], m16[j + 8]);
#pragma unroll
        for (int j = 0; j < 4; ++j)  m4[j] = fmaxf(m8[j], m8[j + 4]);
        m2[0] = fmaxf(m4[0], m4[2]); m2[1] = fmaxf(m4[1], m4[3]);
        float mx = fmaxf(m2[0], m2[1]);

        float e[32];
#pragma unroll
        for (int j = 0; j < 32; ++j) e[j] = __expf(v[j] - mx);
        float s16[16], s8[8], s4[4], s2[2];
#pragma unroll
        for (int j = 0; j < 16; ++j) s16[j] = e[j] + e[j + 16];
#pragma unroll
        for (int j = 0; j < 8; ++j)  s8[j] = s16[j] + s16[j + 8];
#pragma unroll
        for (int j = 0; j < 4; ++j)  s4[j] = s8[j] + s8[j + 4];
        s2[0] = s4[0] + s4[2]; s2[1] = s4[1] + s4[3];
        float sum = s2[0] + s2[1];

        float sn = emit + mx + __logf(sum);
        score = m ? sn : score;
        emit = emit_n;
    }

    float zt = score + trans[STOP_ * 32 + k];
    float mx = zt;
#pragma unroll
    for (int o = 16; o; o >>= 1) mx = fmaxf(mx, __shfl_xor_sync(0xffffffffu, mx, o));
    float es = __expf(zt - mx);
#pragma unroll
    for (int o = 16; o; o >>= 1) es += __shfl_xor_sync(0xffffffffu, es, o);
    float Z = mx + __logf(es);

    float gs = 0.f;
    int len = 0;
    for (int i = k; i < T_; i += 32) {
        int m = mask[b * T_ + i];
        len += m;
        if (i < T_ - 1 && m) {
            int g1 = gold[b * T_ + i + 1];
            int g0 = gold[b * T_ + i];
            gs += g_htag[((size_t)i * B_ + b) * 32 + g1] + trans[g1 * 32 + g0];
        }
    }
#pragma unroll
    for (int o = 16; o; o >>= 1) {
        gs  += __shfl_xor_sync(0xffffffffu, gs, o);
        len += __shfl_xor_sync(0xffffffffu, len, o);
    }
    if (k == 0) {
        int last = gold[b * T_ + len - 1];
        out[b] = Z - (gs + trans[STOP_ * 32 + last]);
    }
}

// =========================================================================
extern "C" void kernel_launch(void* const* d_in, const int* in_sizes, int n_in,
                              void* d_out, int out_size)
{
    const int*   inp   = (const int*)  d_in[0];
    const int*   gold  = (const int*)  d_in[1];
    const int*   mask  = (const int*)  d_in[2];
    const float* emb   = (const float*)d_in[3];
    const float* Wih_f = (const float*)d_in[4];
    const float* Whh_f = (const float*)d_in[5];
    const float* b_f   = (const float*)d_in[6];
    const float* Wih_b = (const float*)d_in[7];
    const float* Whh_b = (const float*)d_in[8];
    const float* b_b   = (const float*)d_in[9];
    const float* W_tag = (const float*)d_in[10];
    const float* b_tag = (const float*)d_in[11];
    const float* trans = (const float*)d_in[12];
    float* out = (float*)d_out;
    (void)in_sizes; (void)n_in; (void)out_size;

    cudaFuncSetAttribute(k1_mma,  cudaFuncAttributeMaxDynamicSharedMemorySize, K1_SMEM);
    cudaFuncSetAttribute(k2_lstm, cudaFuncAttributeMaxDynamicSharedMemorySize, K2_SMEM);

    k0_conv<<<8704, 256>>>(inp, emb, Wih_f, Wih_b);
    k3_wt<<<1, 512>>>(W_tag);
    k1_mma<<<dim3(16, 256), 256, K1_SMEM>>>(b_f, b_b);
    k2_lstm<<<128, 256, K2_SMEM>>>(Whh_f, Whh_b, mask);
    k4_htag<<<(T_ * B_) / 8, 256>>>(b_tag);
    k5_crf<<<B_, 32>>>(mask, gold, trans, out);
}

// round 11
// speedup vs baseline: 2.3620x; 1.5745x over previous
#include <cuda_runtime.h>
#include <cuda_bf16.h>
#include <cstdint>
#include <cstddef>

#define T_ 512
#define B_ 64
#define HD_ 256
#define STOP_ 30

// single dynamic-smem symbol
extern __shared__ __align__(16) char dyn_smem[];

// ---------------- device scratch ----------------
__device__ float g_xw[(size_t)2 * T_ * B_ * 1024];   // [dir][t][b][4H]
__device__ float g_h[(size_t)2 * T_ * B_ * HD_];     // [dir][t][b][H]
__device__ float g_htag[(size_t)T_ * B_ * 32];
__device__ float g_Wt[512 * 32];
__device__ __nv_bfloat16 g_ahi[(size_t)32768 * 256];
__device__ __nv_bfloat16 g_alo[(size_t)32768 * 256];
__device__ __nv_bfloat16 g_bhi[(size_t)2048 * 256];
__device__ __nv_bfloat16 g_blo[(size_t)2048 * 256];
__device__ __align__(16) __nv_bfloat16 g_rhi[16 * 2 * 8 * 256];  // h ring, hi
__device__ __align__(16) __nv_bfloat16 g_rlo[16 * 2 * 8 * 256];  // h ring, lo

// ---------------- PTX helpers ----------------
__device__ __forceinline__ uint32_t smem_u32(const void* p) {
    uint32_t a;
    asm("{ .reg .u64 t; cvta.to.shared.u64 t, %1; cvt.u32.u64 %0, t; }" : "=r"(a) : "l"(p));
    return a;
}
#define LDSM_X4(r, addr) \
    asm volatile("ldmatrix.sync.aligned.m8n8.x4.shared.b16 {%0,%1,%2,%3}, [%4];" \
        : "=r"((r)[0]), "=r"((r)[1]), "=r"((r)[2]), "=r"((r)[3]) : "r"(addr))
#define LDSM_X2(r, addr) \
    asm volatile("ldmatrix.sync.aligned.m8n8.x2.shared.b16 {%0,%1}, [%2];" \
        : "=r"((r)[0]), "=r"((r)[1]) : "r"(addr))
__device__ __forceinline__ void mma16816(float* c, const uint32_t* a, const uint32_t* b) {
    asm volatile("mma.sync.aligned.m16n8k16.row.col.f32.bf16.bf16.f32 "
        "{%0,%1,%2,%3}, {%4,%5,%6,%7}, {%8,%9}, {%0,%1,%2,%3};"
        : "+f"(c[0]), "+f"(c[1]), "+f"(c[2]), "+f"(c[3])
        : "r"(a[0]), "r"(a[1]), "r"(a[2]), "r"(a[3]), "r"(b[0]), "r"(b[1]));
}

// =========================================================================
// K0: gather emb rows + split-convert A and B to bf16 hi/lo. (unchanged)
// =========================================================================
__global__ __launch_bounds__(256) void k0_conv(
    const int* __restrict__ inp, const float* __restrict__ emb,
    const float* __restrict__ Wih_f, const float* __restrict__ Wih_b)
{
    size_t u = (size_t)blockIdx.x * 256 + threadIdx.x;   // float4 index
    const float* src;
    __nv_bfloat16 *dhi, *dlo;
    size_t off;
    if (u < 2097152) {
        int r = (int)(u >> 6);
        int q = (int)(u & 63);
        int tok = inp[(r & 63) * T_ + (r >> 6)];
        src = emb + (size_t)tok * 256 + q * 4;
        off = (size_t)r * 256 + q * 4;
        dhi = g_ahi; dlo = g_alo;
    } else {
        size_t v = u - 2097152;
        if (v >= 131072) return;
        int r = (int)(v >> 6);
        int q = (int)(v & 63);
        src = (r < 1024 ? Wih_f + (size_t)r * 256
                        : Wih_b + (size_t)(r - 1024) * 256) + q * 4;
        off = (size_t)r * 256 + q * 4;
        dhi = g_bhi; dlo = g_blo;
    }
    float4 a = *(const float4*)src;
    __nv_bfloat162 h0 = __floats2bfloat162_rn(a.x, a.y);
    __nv_bfloat162 h1 = __floats2bfloat162_rn(a.z, a.w);
    __nv_bfloat162 l0 = __floats2bfloat162_rn(a.x - __bfloat162float(h0.x),
                                              a.y - __bfloat162float(h0.y));
    __nv_bfloat162 l1 = __floats2bfloat162_rn(a.z - __bfloat162float(h1.x),
                                              a.w - __bfloat162float(h1.y));
    *(uint2*)(dhi + off) = make_uint2(*(uint32_t*)&h0, *(uint32_t*)&h1);
    *(uint2*)(dlo + off) = make_uint2(*(uint32_t*)&l0, *(uint32_t*)&l1);
}

// =========================================================================
// K1: xW = A @ B^T + bias via mma.sync bf16 split (unchanged from R10).
// =========================================================================
#define K1_STR  72
#define K1_AHI  0
#define K1_ALO  (128 * K1_STR)
#define K1_BHI  (2 * 128 * K1_STR)
#define K1_BLO  (3 * 128 * K1_STR)
#define K1_BIAS_B (4 * 128 * K1_STR * 2)
#define K1_SMEM (K1_BIAS_B + 512 + 128)

__global__ __launch_bounds__(256, 2) void k1_mma(
    const float* __restrict__ b_f, const float* __restrict__ b_b)
{
    __nv_bfloat16* smb = (__nv_bfloat16*)dyn_smem;
    float* sbias = (float*)(dyn_smem + K1_BIAS_B);
    const uint32_t sA = smem_u32(smb);
    const int tid = threadIdx.x;
    const int wid = tid >> 5, lane = tid & 31;
    const int row0 = blockIdx.y * 128;
    const int col0 = blockIdx.x * 128;
    const int dir = col0 >> 10, gi0 = col0 & 1023;
    const int wm = wid >> 2, wn = wid & 3;

    if (tid < 128) {
        int g = col0 + tid;
        sbias[tid] = (g < 1024) ? b_f[g] : b_b[g - 1024];
    }

    float acc[4][4][4];
#pragma unroll
    for (int i = 0; i < 4; ++i)
#pragma unroll
        for (int j = 0; j < 4; ++j)
#pragma unroll
            for (int e = 0; e < 4; ++e) acc[i][j][e] = 0.f;

    for (int kc = 0; kc < 4; ++kc) {
        __syncthreads();
        {
            int r  = tid >> 1;
            int g2 = (tid & 1) * 4;
            size_t abase = (size_t)(row0 + r) * 256 + kc * 64 + g2 * 8;
            size_t bbase = (size_t)(col0 + r) * 256 + kc * 64 + g2 * 8;
            int so = r * K1_STR + g2 * 8;
#pragma unroll
            for (int i = 0; i < 4; ++i) {
                *(uint4*)(smb + K1_AHI + so + i * 8) = *(const uint4*)(g_ahi + abase + i * 8);
                *(uint4*)(smb + K1_ALO + so + i * 8) = *(const uint4*)(g_alo + abase + i * 8);
                *(uint4*)(smb + K1_BHI + so + i * 8) = *(const uint4*)(g_bhi + bbase + i * 8);
                *(uint4*)(smb + K1_BLO + so + i * 8) = *(const uint4*)(g_blo + bbase + i * 8);
            }
        }
        __syncthreads();

#pragma unroll
        for (int ks = 0; ks < 4; ++ks) {
            uint32_t bh[4][2], bl[4][2];
#pragma unroll
            for (int nf = 0; nf < 4; ++nf) {
                int nrow = wn * 32 + nf * 8 + (lane & 7);
                int kof  = ks * 16 + ((lane >> 3) & 1) * 8;
                LDSM_X2(bh[nf], sA + (uint32_t)(K1_BHI + nrow * K1_STR + kof) * 2);
                LDSM_X2(bl[nf], sA + (uint32_t)(K1_BLO + nrow * K1_STR + kof) * 2);
            }
            uint32_t af[4][4];
            {
                int mrow = wm * 64 + (lane & 15);
                int kof  = ks * 16 + (lane >> 4) * 8;
#pragma unroll
                for (int mf = 0; mf < 4; ++mf)
                    LDSM_X4(af[mf], sA + (uint32_t)(K1_AHI + (mrow + mf * 16) * K1_STR + kof) * 2);
#pragma unroll
                for (int mf = 0; mf < 4; ++mf)
#pragma unroll
                    for (int nf = 0; nf < 4; ++nf) {
                        mma16816(acc[mf][nf], af[mf], bh[nf]);
                        mma16816(acc[mf][nf], af[mf], bl[nf]);
                    }
#pragma unroll
                for (int mf = 0; mf < 4; ++mf)
                    LDSM_X4(af[mf], sA + (uint32_t)(K1_ALO + (mrow + mf * 16) * K1_STR + kof) * 2);
#pragma unroll
                for (int mf = 0; mf < 4; ++mf)
#pragma unroll
                    for (int nf = 0; nf < 4; ++nf)
                        mma16816(acc[mf][nf], af[mf], bh[nf]);
            }
        }
    }

    const int gq = lane >> 2, tq = lane & 3;
#pragma unroll
    for (int mf = 0; mf < 4; ++mf)
#pragma unroll
        for (int i2 = 0; i2 < 2; ++i2) {
            int m = wm * 64 + mf * 16 + gq + i2 * 8;
            int r = row0 + m;
            int t = r >> 6, b = r & 63;
            float* dst = g_xw + (((size_t)dir * T_ + t) * B_ + b) * 1024 + gi0;
#pragma unroll
            for (int nf = 0; nf < 4; ++nf) {
                int n = wn * 32 + nf * 8 + tq * 2;
                float2 v;
                v.x = acc[mf][nf][i2 * 2 + 0] + sbias[n];
                v.y = acc[mf][nf][i2 * 2 + 1] + sbias[n + 1];
                *(float2*)(dst + n) = v;
            }
        }
}

// =========================================================================
// K2: BiLSTM recurrence on tensor cores (mma.sync bf16 split, 3 passes).
// 128 CTAs, clusters of 8 = (dir, 8-batch group). Rank owns 32 j.
// Per step per CTA: gates[16(8 real)M x 128N] = H[16x256] @ Whh_slice^T.
// Whh slice bf16 hi/lo resident in SMEM; h exchanged via gmem ring.
// =========================================================================
#define W_STR 264
#define OFF_WHI 0
#define OFF_WLO 33792
#define OFF_AHI 67584
#define OFF_ALO 71808
#define OFF_GATE_B 152064
#define OFF_MSK_B  156416
#define K2_SMEM    160512

__device__ __forceinline__ float fsig(float x) { return 1.f / (1.f + __expf(-x)); }

__global__ __launch_bounds__(256, 1) __cluster_dims__(8, 1, 1)
void k2_lstm(const float* __restrict__ Whh_f, const float* __restrict__ Whh_b,
             const int* __restrict__ mask)
{
    __nv_bfloat16* SM = (__nv_bfloat16*)dyn_smem;
    float* sg  = (float*)(dyn_smem + OFF_GATE_B);   // [4 g][8 b][34]
    char*  msk = (char*)(dyn_smem + OFF_MSK_B);     // [8 b][512]
    const uint32_t sA = smem_u32(dyn_smem);

    const int tid  = threadIdx.x;
    const int wid  = tid >> 5;
    const int lane = tid & 31;
    const int rank = blockIdx.x & 7;
    const int cid  = blockIdx.x >> 3;
    const int d    = cid >> 3;
    const int G    = cid & 7;
    // cell ownership: this thread owns (batch cb, unit cj)
    const int cb = tid >> 5;            // 0..7
    const int cj = tid & 31;            // 0..31
    const int jg = 32 * rank + cj;
    const int bg = 8 * G + cb;          // global batch

    // ---- init: Whh slice -> split bf16 hi/lo in SMEM, [n][k], n = g*32+j
    {
        const float* Whh = d ? Whh_b : Whh_f;
        for (int n = wid; n < 128; n += 8) {
            const float* row = Whh + (size_t)((n >> 5) * 256 + 32 * rank + (n & 31)) * 256;
#pragma unroll
            for (int k0 = lane * 4; k0 < 256; k0 += 128) {
                float4 v = *(const float4*)(row + k0);
                __nv_bfloat162 h0 = __floats2bfloat162_rn(v.x, v.y);
                __nv_bfloat162 h1 = __floats2bfloat162_rn(v.z, v.w);
                __nv_bfloat162 l0 = __floats2bfloat162_rn(v.x - __bfloat162float(h0.x),
                                                          v.y - __bfloat162float(h0.y));
                __nv_bfloat162 l1 = __floats2bfloat162_rn(v.z - __bfloat162float(h1.x),
                                                          v.w - __bfloat162float(h1.y));
                *(uint2*)(SM + OFF_WHI + n * W_STR + k0) = make_uint2(*(uint32_t*)&h0, *(uint32_t*)&h1);
                *(uint2*)(SM + OFF_WLO + n * W_STR + k0) = make_uint2(*(uint32_t*)&l0, *(uint32_t*)&l1);
            }
        }
        // zero H matrices (incl. pad rows 8..15)
        __nv_bfloat16 z = __float2bfloat16(0.f);
        for (int u = tid; u < 16 * W_STR; u += 256) {
            SM[OFF_AHI + u] = z;
            SM[OFF_ALO + u] = z;
        }
        for (int u = tid; u < 4096; u += 256)
            msk[u] = (char)mask[(8 * G + (u >> 9)) * T_ + (u & 511)];
    }
    __syncthreads();

    float c = 0.f, h = 0.f;
    const int dt = d ? -1 : 1;
    int t = d ? (T_ - 1) : 0;

    float px[4];
    {
        const float* xp = g_xw + (((size_t)d * T_ + t) * B_ + bg) * 1024 + jg;
        px[0] = xp[0]; px[1] = xp[256]; px[2] = xp[512]; px[3] = xp[768];
    }

    // mma index precompute (identical frag patterns to k1, proven)
    const int mrow  = lane & 15;
    const int akof  = (lane >> 4) * 8;
    const int brow  = wid * 16 + (lane & 7);
    const int bkof  = ((lane >> 3) & 1) * 8;
    const int gq = lane >> 2, tq = lane & 3;

    for (int s = 0; s < T_; ++s) {
        // ---- load peers' h (hi/lo) from ring into SMEM rows 0..7
        if (s > 0) {
            int row = tid >> 5;
            int k   = (tid & 31) * 8;
            size_t ri = ((size_t)(cid * 2 + (s & 1)) * 8 + row) * 256 + k;
            *(uint4*)(SM + OFF_AHI + row * W_STR + k) = __ldcg((const uint4*)(g_rhi + ri));
            *(uint4*)(SM + OFF_ALO + row * W_STR + k) = __ldcg((const uint4*)(g_rlo + ri));
        }
        // prefetch next step's xw (hidden under mma phase)
        float nx[4];
        {
            int tn = (s + 1 < T_) ? t + dt : t;
            const float* xp = g_xw + (((size_t)d * T_ + tn) * B_ + bg) * 1024 + jg;
            nx[0] = xp[0]; nx[1] = xp[256]; nx[2] = xp[512]; nx[3] = xp[768];
        }
        __syncthreads();

        // ---- tensor-core gate GEMM: 3 passes, fp32 accum
        float acc0[4] = {0.f, 0.f, 0.f, 0.f};
        float acc1[4] = {0.f, 0.f, 0.f, 0.f};
#pragma unroll
        for (int ks = 0; ks < 16; ++ks) {
            const int k = ks * 16;
            uint32_t ah[4], al[4], bh0[2], bh1[2], bl0[2], bl1[2];
            LDSM_X4(ah, sA + (uint32_t)(OFF_AHI + mrow * W_STR + k + akof) * 2);
            LDSM_X4(al, sA + (uint32_t)(OFF_ALO + mrow * W_STR + k + akof) * 2);
            LDSM_X2(bh0, sA + (uint32_t)(OFF_WHI + brow * W_STR + k + bkof) * 2);
            LDSM_X2(bh1, sA + (uint32_t)(OFF_WHI + (brow + 8) * W_STR + k + bkof) * 2);
            LDSM_X2(bl0, sA + (uint32_t)(OFF_WLO + brow * W_STR + k + bkof) * 2);
            LDSM_X2(bl1, sA + (uint32_t)(OFF_WLO + (brow + 8) * W_STR + k + bkof) * 2);
            mma16816(acc0, ah, bh0);  mma16816(acc1, ah, bh1);
            mma16816(acc0, ah, bl0);  mma16816(acc1, ah, bl1);
            mma16816(acc0, al, bh0);  mma16816(acc1, al, bh1);
        }

        // ---- scatter gates to SMEM (rows 0..7 = real batches)
        if (gq < 8) {
            {
                int n = wid * 16 + tq * 2;
                int g = n >> 5, j = n & 31;
                sg[(g * 8 + gq) * 34 + j]     = acc0[0];
                sg[(g * 8 + gq) * 34 + j + 1] = acc0[1];
            }
            {
                int n = wid * 16 + 8 + tq * 2;
                int g = n >> 5, j = n & 31;
                sg[(g * 8 + gq) * 34 + j]     = acc1[0];
                sg[(g * 8 + gq) * 34 + j + 1] = acc1[1];
            }
        }
        __syncthreads();

        // ---- cell update (1 cell per thread)
        {
            int m = msk[cb * 512 + t];
            float zi = sg[(0 * 8 + cb) * 34 + cj] + px[0];
            float zf = sg[(1 * 8 + cb) * 34 + cj] + px[1];
            float zg = sg[(2 * 8 + cb) * 34 + cj] + px[2];
            float zo = sg[(3 * 8 + cb) * 34 + cj] + px[3];
            float cn = fsig(zf) * c + fsig(zi) * tanhf(zg);
            float hn = fsig(zo) * tanhf(cn);
            if (m) { c = cn; h = hn; }

            g_h[(((size_t)d * T_ + t) * B_ + bg) * HD_ + jg] = h;
            __nv_bfloat16 hi = __float2bfloat16(h);
            __nv_bfloat16 lo = __float2bfloat16(h - __bfloat162float(hi));
            size_t ri = ((size_t)(cid * 2 + ((s + 1) & 1)) * 8 + cb) * 256 + jg;
            g_rhi[ri] = hi;
            g_rlo[ri] = lo;
        }
        px[0] = nx[0]; px[1] = nx[1]; px[2] = nx[2]; px[3] = nx[3];

        asm volatile("barrier.cluster.arrive.aligned;" ::: "memory");
        asm volatile("barrier.cluster.wait.aligned;"   ::: "memory");
        t += dt;
    }
}

// =========================================================================
// K3: W_tag transpose
// =========================================================================
__global__ void k3_wt(const float* __restrict__ W_tag)
{
    int kk = threadIdx.x;
    for (int k = 0; k < 32; ++k)
        g_Wt[kk * 32 + k] = W_tag[k * 512 + kk];
}

// =========================================================================
// K4: h_tag = [h_f,h_b] @ W_tag^T + b_tag
// =========================================================================
__global__ __launch_bounds__(256) void k4_htag(const float* __restrict__ b_tag)
{
    __shared__ float hrow[8][512];
    const int tid = threadIdx.x;
    const int r0 = blockIdx.x * 8;

    for (int u = tid; u < 1024; u += 256) {
        int rl = u >> 7;
        int off = (u & 127) * 4;
        int r = r0 + rl;
        int t = r >> 6, b = r & 63;
        const float* src = (off < 256)
            ? &g_h[(((size_t)0 * T_ + t) * B_ + b) * HD_ + off]
            : &g_h[(((size_t)1 * T_ + t) * B_ + b) * HD_ + off - 256];
        *(float4*)&hrow[rl][off] = *(const float4*)src;
    }
    __syncthreads();

    const int rl = tid >> 5;
    const int k  = tid & 31;
    float acc = b_tag[k];
#pragma unroll 8
    for (int kk = 0; kk < 512; ++kk)
        acc = fmaf(hrow[rl][kk], g_Wt[kk * 32 + k], acc);
    g_htag[(size_t)(r0 + rl) * 32 + k] = acc;
}

// =========================================================================
// K5: CRF forward + gold score (unchanged).
// =========================================================================
__global__ __launch_bounds__(32) void k5_crf(
    const int* __restrict__ mask, const int* __restrict__ gold,
    const float* __restrict__ trans, float* __restrict__ out)
{
    __shared__ unsigned mw[16];
    const int b = blockIdx.x;
    const int k = threadIdx.x;

    float trow[32];
#pragma unroll
    for (int j = 0; j < 32; ++j) trow[j] = trans[k * 32 + j];

    for (int blk = 0; blk < 16; ++blk) {
        int bit = mask[b * T_ + blk * 32 + k];
        unsigned wword = __ballot_sync(0xffffffffu, bit != 0);
        if (k == 0) mw[blk] = wword;
    }
    __syncwarp();

    float score = (k == STOP_) ? 0.f : -10000.f;
    float emit = g_htag[((size_t)0 * B_ + b) * 32 + k];

    for (int t = 0; t < T_; ++t) {
        int tn = (t + 1 < T_) ? t + 1 : t;
        float emit_n = g_htag[((size_t)tn * B_ + b) * 32 + k];
        int m = (mw[t >> 5] >> (t & 31)) & 1;

        float v[32];
#pragma unroll
        for (int j = 0; j < 32; ++j)
            v[j] = __shfl_sync(0xffffffffu, score, j) + trow[j];

        float m16[16], m8[8], m4[4], m2[2];
#pragma unroll
        for (int j = 0; j < 16; ++j) m16[j] = fmaxf(v[j], v[j + 16]);
#pragma unroll
        for (int j = 0; j < 8; ++j)  m8[j] = fmaxf(m16[j], m16[j + 8]);
#pragma unroll
        for (int j = 0; j < 4; ++j)  m4[j] = fmaxf(m8[j], m8[j + 4]);
        m2[0] = fmaxf(m4[0], m4[2]); m2[1] = fmaxf(m4[1], m4[3]);
        float mx = fmaxf(m2[0], m2[1]);

        float e[32];
#pragma unroll
        for (int j = 0; j < 32; ++j) e[j] = __expf(v[j] - mx);
        float s16[16], s8[8], s4[4], s2[2];
#pragma unroll
        for (int j = 0; j < 16; ++j) s16[j] = e[j] + e[j + 16];
#pragma unroll
        for (int j = 0; j < 8; ++j)  s8[j] = s16[j] + s16[j + 8];
#pragma unroll
        for (int j = 0; j < 4; ++j)  s4[j] = s8[j] + s8[j + 4];
        s2[0] = s4[0] + s4[2]; s2[1] = s4[1] + s4[3];
        float sum = s2[0] + s2[1];

        float sn = emit + mx + __logf(sum);
        score = m ? sn : score;
        emit = emit_n;
    }

    float zt = score + trans[STOP_ * 32 + k];
    float mx = zt;
#pragma unroll
    for (int o = 16; o; o >>= 1) mx = fmaxf(mx, __shfl_xor_sync(0xffffffffu, mx, o));
    float es = __expf(zt - mx);
#pragma unroll
    for (int o = 16; o; o >>= 1) es += __shfl_xor_sync(0xffffffffu, es, o);
    float Z = mx + __logf(es);

    float gs = 0.f;
    int len = 0;
    for (int i = k; i < T_; i += 32) {
        int m = mask[b * T_ + i];
        len += m;
        if (i < T_ - 1 && m) {
            int g1 = gold[b * T_ + i + 1];
            int g0 = gold[b * T_ + i];
            gs += g_htag[((size_t)i * B_ + b) * 32 + g1] + trans[g1 * 32 + g0];
        }
    }
#pragma unroll
    for (int o = 16; o; o >>= 1) {
        gs  += __shfl_xor_sync(0xffffffffu, gs, o);
        len += __shfl_xor_sync(0xffffffffu, len, o);
    }
    if (k == 0) {
        int last = gold[b * T_ + len - 1];
        out[b] = Z - (gs + trans[STOP_ * 32 + last]);
    }
}

// =========================================================================
extern "C" void kernel_launch(void* const* d_in, const int* in_sizes, int n_in,
                              void* d_out, int out_size)
{
    const int*   inp   = (const int*)  d_in[0];
    const int*   gold  = (const int*)  d_in[1];
    const int*   mask  = (const int*)  d_in[2];
    const float* emb   = (const float*)d_in[3];
    const float* Wih_f = (const float*)d_in[4];
    const float* Whh_f = (const float*)d_in[5];
    const float* b_f   = (const float*)d_in[6];
    const float* Wih_b = (const float*)d_in[7];
    const float* Whh_b = (const float*)d_in[8];
    const float* b_b   = (const float*)d_in[9];
    const float* W_tag = (const float*)d_in[10];
    const float* b_tag = (const float*)d_in[11];
    const float* trans = (const float*)d_in[12];
    float* out = (float*)d_out;
    (void)in_sizes; (void)n_in; (void)out_size;

    cudaFuncSetAttribute(k1_mma,  cudaFuncAttributeMaxDynamicSharedMemorySize, K1_SMEM);
    cudaFuncSetAttribute(k2_lstm, cudaFuncAttributeMaxDynamicSharedMemorySize, K2_SMEM);

    k0_conv<<<8704, 256>>>(inp, emb, Wih_f, Wih_b);
    k3_wt<<<1, 512>>>(W_tag);
    k1_mma<<<dim3(16, 256), 256, K1_SMEM>>>(b_f, b_b);
    k2_lstm<<<128, 256, K2_SMEM>>>(Whh_f, Whh_b, mask);
    k4_htag<<<(T_ * B_) / 8, 256>>>(b_tag);
    k5_crf<<<B_, 32>>>(mask, gold, trans, out);
}

// round 12
// speedup vs baseline: 3.0848x; 1.3060x over previous
#include <cuda_runtime.h>
#include <cuda_bf16.h>
#include <cstdint>
#include <cstddef>

#define T_ 512
#define B_ 64
#define HD_ 256
#define STOP_ 30

// single dynamic-smem symbol
extern __shared__ __align__(16) char dyn_smem[];

// ---------------- device scratch ----------------
__device__ float g_xw[(size_t)2 * T_ * B_ * 1024];   // [dir][t][b][4H]
__device__ float g_h[(size_t)2 * T_ * B_ * HD_];     // [dir][t][b][H]
__device__ float g_htag[(size_t)T_ * B_ * 32];
__device__ float g_Wt[512 * 32];
__device__ __nv_bfloat16 g_ahi[(size_t)32768 * 256];
__device__ __nv_bfloat16 g_alo[(size_t)32768 * 256];
__device__ __nv_bfloat16 g_bhi[(size_t)2048 * 256];
__device__ __nv_bfloat16 g_blo[(size_t)2048 * 256];

// ---------------- PTX helpers ----------------
__device__ __forceinline__ uint32_t smem_u32(const void* p) {
    uint32_t a;
    asm("{ .reg .u64 t; cvta.to.shared.u64 t, %1; cvt.u32.u64 %0, t; }" : "=r"(a) : "l"(p));
    return a;
}
#define LDSM_X4(r, addr) \
    asm volatile("ldmatrix.sync.aligned.m8n8.x4.shared.b16 {%0,%1,%2,%3}, [%4];" \
        : "=r"((r)[0]), "=r"((r)[1]), "=r"((r)[2]), "=r"((r)[3]) : "r"(addr))
#define LDSM_X2(r, addr) \
    asm volatile("ldmatrix.sync.aligned.m8n8.x2.shared.b16 {%0,%1}, [%2];" \
        : "=r"((r)[0]), "=r"((r)[1]) : "r"(addr))
__device__ __forceinline__ void mma16816(float* c, const uint32_t* a, const uint32_t* b) {
    asm volatile("mma.sync.aligned.m16n8k16.row.col.f32.bf16.bf16.f32 "
        "{%0,%1,%2,%3}, {%4,%5,%6,%7}, {%8,%9}, {%0,%1,%2,%3};"
        : "+f"(c[0]), "+f"(c[1]), "+f"(c[2]), "+f"(c[3])
        : "r"(a[0]), "r"(a[1]), "r"(a[2]), "r"(a[3]), "r"(b[0]), "r"(b[1]));
}
#define MBAR_INIT(mb, c) asm volatile("mbarrier.init.shared.b64 [%0], %1;" :: "r"(mb), "r"((uint32_t)(c)) : "memory")
__device__ __forceinline__ void mbar_wait_cl(uint32_t mb, uint32_t parity) {
    asm volatile(
        "{\n\t.reg .pred P;\n\t"
        "WL_%=:\n\t"
        "mbarrier.try_wait.parity.acquire.cluster.shared::cta.b64 P, [%0], %1, 0x989680;\n\t"
        "@P bra WD_%=;\n\t"
        "bra WL_%=;\n\t"
        "WD_%=:\n\t}"
        :: "r"(mb), "r"(parity) : "memory");
}
__device__ __forceinline__ uint32_t mapa_rank(uint32_t a, uint32_t r) {
    uint32_t o;
    asm("mapa.shared::cluster.u32 %0, %1, %2;" : "=r"(o) : "r"(a), "r"(r));
    return o;
}
#define STS_CL_V4(addr, v) \
    asm volatile("st.shared::cluster.v4.b32 [%0], {%1,%2,%3,%4};" \
        :: "r"(addr), "r"((v).x), "r"((v).y), "r"((v).z), "r"((v).w) : "memory")
#define MBAR_ARRIVE_REMOTE(addr) \
    asm volatile("mbarrier.arrive.release.cluster.shared::cluster.b64 _, [%0];" :: "r"(addr) : "memory")

// =========================================================================
// K0: gather emb rows + split-convert A and B to bf16 hi/lo. (unchanged)
// =========================================================================
__global__ __launch_bounds__(256) void k0_conv(
    const int* __restrict__ inp, const float* __restrict__ emb,
    const float* __restrict__ Wih_f, const float* __restrict__ Wih_b)
{
    size_t u = (size_t)blockIdx.x * 256 + threadIdx.x;
    const float* src;
    __nv_bfloat16 *dhi, *dlo;
    size_t off;
    if (u < 2097152) {
        int r = (int)(u >> 6);
        int q = (int)(u & 63);
        int tok = inp[(r & 63) * T_ + (r >> 6)];
        src = emb + (size_t)tok * 256 + q * 4;
        off = (size_t)r * 256 + q * 4;
        dhi = g_ahi; dlo = g_alo;
    } else {
        size_t v = u - 2097152;
        if (v >= 131072) return;
        int r = (int)(v >> 6);
        int q = (int)(v & 63);
        src = (r < 1024 ? Wih_f + (size_t)r * 256
                        : Wih_b + (size_t)(r - 1024) * 256) + q * 4;
        off = (size_t)r * 256 + q * 4;
        dhi = g_bhi; dlo = g_blo;
    }
    float4 a = *(const float4*)src;
    __nv_bfloat162 h0 = __floats2bfloat162_rn(a.x, a.y);
    __nv_bfloat162 h1 = __floats2bfloat162_rn(a.z, a.w);
    __nv_bfloat162 l0 = __floats2bfloat162_rn(a.x - __bfloat162float(h0.x),
                                              a.y - __bfloat162float(h0.y));
    __nv_bfloat162 l1 = __floats2bfloat162_rn(a.z - __bfloat162float(h1.x),
                                              a.w - __bfloat162float(h1.y));
    *(uint2*)(dhi + off) = make_uint2(*(uint32_t*)&h0, *(uint32_t*)&h1);
    *(uint2*)(dlo + off) = make_uint2(*(uint32_t*)&l0, *(uint32_t*)&l1);
}

// =========================================================================
// K1: xW = A @ B^T + bias via mma.sync bf16 split (unchanged from R11).
// =========================================================================
#define K1_STR  72
#define K1_AHI  0
#define K1_ALO  (128 * K1_STR)
#define K1_BHI  (2 * 128 * K1_STR)
#define K1_BLO  (3 * 128 * K1_STR)
#define K1_BIAS_B (4 * 128 * K1_STR * 2)
#define K1_SMEM (K1_BIAS_B + 512 + 128)

__global__ __launch_bounds__(256, 2) void k1_mma(
    const float* __restrict__ b_f, const float* __restrict__ b_b)
{
    __nv_bfloat16* smb = (__nv_bfloat16*)dyn_smem;
    float* sbias = (float*)(dyn_smem + K1_BIAS_B);
    const uint32_t sA = smem_u32(smb);
    const int tid = threadIdx.x;
    const int wid = tid >> 5, lane = tid & 31;
    const int row0 = blockIdx.y * 128;
    const int col0 = blockIdx.x * 128;
    const int dir = col0 >> 10, gi0 = col0 & 1023;
    const int wm = wid >> 2, wn = wid & 3;

    if (tid < 128) {
        int g = col0 + tid;
        sbias[tid] = (g < 1024) ? b_f[g] : b_b[g - 1024];
    }

    float acc[4][4][4];
#pragma unroll
    for (int i = 0; i < 4; ++i)
#pragma unroll
        for (int j = 0; j < 4; ++j)
#pragma unroll
            for (int e = 0; e < 4; ++e) acc[i][j][e] = 0.f;

    for (int kc = 0; kc < 4; ++kc) {
        __syncthreads();
        {
            int r  = tid >> 1;
            int g2 = (tid & 1) * 4;
            size_t abase = (size_t)(row0 + r) * 256 + kc * 64 + g2 * 8;
            size_t bbase = (size_t)(col0 + r) * 256 + kc * 64 + g2 * 8;
            int so = r * K1_STR + g2 * 8;
#pragma unroll
            for (int i = 0; i < 4; ++i) {
                *(uint4*)(smb + K1_AHI + so + i * 8) = *(const uint4*)(g_ahi + abase + i * 8);
                *(uint4*)(smb + K1_ALO + so + i * 8) = *(const uint4*)(g_alo + abase + i * 8);
                *(uint4*)(smb + K1_BHI + so + i * 8) = *(const uint4*)(g_bhi + bbase + i * 8);
                *(uint4*)(smb + K1_BLO + so + i * 8) = *(const uint4*)(g_blo + bbase + i * 8);
            }
        }
        __syncthreads();

#pragma unroll
        for (int ks = 0; ks < 4; ++ks) {
            uint32_t bh[4][2], bl[4][2];
#pragma unroll
            for (int nf = 0; nf < 4; ++nf) {
                int nrow = wn * 32 + nf * 8 + (lane & 7);
                int kof  = ks * 16 + ((lane >> 3) & 1) * 8;
                LDSM_X2(bh[nf], sA + (uint32_t)(K1_BHI + nrow * K1_STR + kof) * 2);
                LDSM_X2(bl[nf], sA + (uint32_t)(K1_BLO + nrow * K1_STR + kof) * 2);
            }
            uint32_t af[4][4];
            {
                int mrow = wm * 64 + (lane & 15);
                int kof  = ks * 16 + (lane >> 4) * 8;
#pragma unroll
                for (int mf = 0; mf < 4; ++mf)
                    LDSM_X4(af[mf], sA + (uint32_t)(K1_AHI + (mrow + mf * 16) * K1_STR + kof) * 2);
#pragma unroll
                for (int mf = 0; mf < 4; ++mf)
#pragma unroll
                    for (int nf = 0; nf < 4; ++nf) {
                        mma16816(acc[mf][nf], af[mf], bh[nf]);
                        mma16816(acc[mf][nf], af[mf], bl[nf]);
                    }
#pragma unroll
                for (int mf = 0; mf < 4; ++mf)
                    LDSM_X4(af[mf], sA + (uint32_t)(K1_ALO + (mrow + mf * 16) * K1_STR + kof) * 2);
#pragma unroll
                for (int mf = 0; mf < 4; ++mf)
#pragma unroll
                    for (int nf = 0; nf < 4; ++nf)
                        mma16816(acc[mf][nf], af[mf], bh[nf]);
            }
        }
    }

    const int gq = lane >> 2, tq = lane & 3;
#pragma unroll
    for (int mf = 0; mf < 4; ++mf)
#pragma unroll
        for (int i2 = 0; i2 < 2; ++i2) {
            int m = wm * 64 + mf * 16 + gq + i2 * 8;
            int r = row0 + m;
            int t = r >> 6, b = r & 63;
            float* dst = g_xw + (((size_t)dir * T_ + t) * B_ + b) * 1024 + gi0;
#pragma unroll
            for (int nf = 0; nf < 4; ++nf) {
                int n = wn * 32 + nf * 8 + tq * 2;
                float2 v;
                v.x = acc[mf][nf][i2 * 2 + 0] + sbias[n];
                v.y = acc[mf][nf][i2 * 2 + 1] + sbias[n + 1];
                *(float2*)(dst + n) = v;
            }
        }
}

// =========================================================================
// K2: BiLSTM recurrence on tensor cores + DSMEM h-exchange.
// Clusters of 8 = (dir, 8-batch group). Rank owns 32 j.
// Double-buffered H tiles in SMEM; producers st.shared::cluster h slices
// into all peers; per-lane mbarrier.arrive.release.cluster (256/phase).
// Skips fully-masked steps (group maxlen) with bulk g_h fill.
// =========================================================================
#define W_STR 264
#define OFF_WHI  0
#define OFF_WLO  33792
#define OFF_A0HI 67584
#define OFF_A1HI (67584 + 8448)
#define BY_SG    168960
#define BY_MSK   173312
#define BY_STG   177408
#define BY_MBAR  178432
#define BY_MAX   178448
#define K2_SMEM  178464

__device__ __forceinline__ float fsig(float x) { return 1.f / (1.f + __expf(-x)); }

__global__ __launch_bounds__(256, 1) __cluster_dims__(8, 1, 1)
void k2_lstm(const float* __restrict__ Whh_f, const float* __restrict__ Whh_b,
             const int* __restrict__ mask)
{
    __nv_bfloat16* SM = (__nv_bfloat16*)dyn_smem;
    float* sg  = (float*)(dyn_smem + BY_SG);    // [4 g][8 b][34]
    char*  msk = dyn_smem + BY_MSK;             // [8 b][512]
    __nv_bfloat16* stgH = (__nv_bfloat16*)(dyn_smem + BY_STG);        // 256
    __nv_bfloat16* stgL = (__nv_bfloat16*)(dyn_smem + BY_STG + 512);  // 256
    int* smax = (int*)(dyn_smem + BY_MAX);
    const uint32_t sb = smem_u32(dyn_smem);

    const int tid  = threadIdx.x;
    const int wid  = tid >> 5;
    const int lane = tid & 31;
    const int rank = blockIdx.x & 7;
    const int cid  = blockIdx.x >> 3;
    const int d    = cid >> 3;
    const int G    = cid & 7;
    const int cb = tid >> 5;            // owned batch (local)
    const int cj = tid & 31;            // owned unit (local)
    const int jg = 32 * rank + cj;
    const int bg = 8 * G + cb;

    // ---- init ----
    if (tid == 0) {
        MBAR_INIT(sb + BY_MBAR, 256);
        MBAR_INIT(sb + BY_MBAR + 8, 256);
        *smax = 0;
    }
    {
        const float* Whh = d ? Whh_b : Whh_f;
        for (int n = wid; n < 128; n += 8) {
            const float* row = Whh + (size_t)((n >> 5) * 256 + 32 * rank + (n & 31)) * 256;
#pragma unroll
            for (int k0 = lane * 4; k0 < 256; k0 += 128) {
                float4 v = *(const float4*)(row + k0);
                __nv_bfloat162 h0 = __floats2bfloat162_rn(v.x, v.y);
                __nv_bfloat162 h1 = __floats2bfloat162_rn(v.z, v.w);
                __nv_bfloat162 l0 = __floats2bfloat162_rn(v.x - __bfloat162float(h0.x),
                                                          v.y - __bfloat162float(h0.y));
                __nv_bfloat162 l1 = __floats2bfloat162_rn(v.z - __bfloat162float(h1.x),
                                                          v.w - __bfloat162float(h1.y));
                *(uint2*)(SM + OFF_WHI + n * W_STR + k0) = make_uint2(*(uint32_t*)&h0, *(uint32_t*)&h1);
                *(uint2*)(SM + OFF_WLO + n * W_STR + k0) = make_uint2(*(uint32_t*)&l0, *(uint32_t*)&l1);
            }
        }
        __nv_bfloat16 z = __float2bfloat16(0.f);
        for (int u = tid; u < 16896; u += 256)        // both H buffers (hi+lo)
            SM[OFF_A0HI + u] = z;
        for (int u = tid; u < 4096; u += 256)
            msk[u] = (char)mask[(8 * G + (u >> 9)) * T_ + (u & 511)];
    }
    __syncthreads();
    // group maxlen = length of first (longest) batch in group
    {
        int part = (int)msk[tid] + (int)msk[256 + tid];
#pragma unroll
        for (int o = 16; o; o >>= 1) part += __shfl_xor_sync(0xffffffffu, part, o);
        if (lane == 0) atomicAdd(smax, part);
    }
    __syncthreads();
    const int maxlen = *smax;

    // cluster-wide: mbarrier init + zeroed buffers visible before any remote write
    asm volatile("barrier.cluster.arrive.aligned;" ::: "memory");
    asm volatile("barrier.cluster.wait.aligned;"   ::: "memory");

    const int dt = d ? -1 : 1;
    int t = d ? (maxlen - 1) : 0;

    // bwd: h == 0 on fully-masked tail
    if (d == 1) {
        for (int tt = maxlen; tt < T_; ++tt)
            g_h[(((size_t)1 * T_ + tt) * B_ + bg) * HD_ + jg] = 0.f;
    }

    float c = 0.f, h = 0.f;
    float px[4];
    {
        const float* xp = g_xw + (((size_t)d * T_ + t) * B_ + bg) * 1024 + jg;
        px[0] = xp[0]; px[1] = xp[256]; px[2] = xp[512]; px[3] = xp[768];
    }

    const int mrow  = lane & 15;
    const int akof  = (lane >> 4) * 8;
    const int brow  = wid * 16 + (lane & 7);
    const int bkof  = ((lane >> 3) & 1) * 8;
    const int gq = lane >> 2, tq = lane & 3;
    int ph0 = 0, ph1 = 0;

    for (int s = 0; s < maxlen; ++s) {
        const int buf  = s & 1;
        const int nbuf = buf ^ 1;
        const int a_hi = OFF_A0HI + buf * 8448;
        const int a_lo = a_hi + 4224;

        if (s > 0) {
            uint32_t mb = sb + BY_MBAR + buf * 8;
            if (buf) { mbar_wait_cl(mb, (uint32_t)ph1); ph1 ^= 1; }
            else     { mbar_wait_cl(mb, (uint32_t)ph0); ph0 ^= 1; }
        }
        // prefetch next step's xw
        float nx[4];
        {
            int tn = (s + 1 < maxlen) ? t + dt : t;
            const float* xp = g_xw + (((size_t)d * T_ + tn) * B_ + bg) * 1024 + jg;
            nx[0] = xp[0]; nx[1] = xp[256]; nx[2] = xp[512]; nx[3] = xp[768];
        }

        // ---- tensor-core gate GEMM (3 passes, fp32 accum) ----
        float acc0[4] = {0.f, 0.f, 0.f, 0.f};
        float acc1[4] = {0.f, 0.f, 0.f, 0.f};
#pragma unroll
        for (int ks = 0; ks < 16; ++ks) {
            const int k = ks * 16;
            uint32_t ah[4], al[4], bh0[2], bh1[2], bl0[2], bl1[2];
            LDSM_X4(ah, sb + (uint32_t)(a_hi + mrow * W_STR + k + akof) * 2);
            LDSM_X4(al, sb + (uint32_t)(a_lo + mrow * W_STR + k + akof) * 2);
            LDSM_X2(bh0, sb + (uint32_t)(OFF_WHI + brow * W_STR + k + bkof) * 2);
            LDSM_X2(bh1, sb + (uint32_t)(OFF_WHI + (brow + 8) * W_STR + k + bkof) * 2);
            LDSM_X2(bl0, sb + (uint32_t)(OFF_WLO + brow * W_STR + k + bkof) * 2);
            LDSM_X2(bl1, sb + (uint32_t)(OFF_WLO + (brow + 8) * W_STR + k + bkof) * 2);
            mma16816(acc0, ah, bh0);  mma16816(acc1, ah, bh1);
            mma16816(acc0, ah, bl0);  mma16816(acc1, ah, bl1);
            mma16816(acc0, al, bh0);  mma16816(acc1, al, bh1);
        }

        // ---- scatter gates (rows 0..7 real) ----
        if (gq < 8) {
            {
                int n = wid * 16 + tq * 2;
                int g = n >> 5, j = n & 31;
                sg[(g * 8 + gq) * 34 + j]     = acc0[0];
                sg[(g * 8 + gq) * 34 + j + 1] = acc0[1];
            }
            {
                int n = wid * 16 + 8 + tq * 2;
                int g = n >> 5, j = n & 31;
                sg[(g * 8 + gq) * 34 + j]     = acc1[0];
                sg[(g * 8 + gq) * 34 + j + 1] = acc1[1];
            }
        }
        __syncthreads();

        // ---- cell update (1 cell per thread) + stage h hi/lo ----
        {
            int m = msk[cb * 512 + t];
            float zi = sg[(0 * 8 + cb) * 34 + cj] + px[0];
            float zf = sg[(1 * 8 + cb) * 34 + cj] + px[1];
            float zg = sg[(2 * 8 + cb) * 34 + cj] + px[2];
            float zo = sg[(3 * 8 + cb) * 34 + cj] + px[3];
            float cn = fsig(zf) * c + fsig(zi) * tanhf(zg);
            float hn = fsig(zo) * tanhf(cn);
            if (m) { c = cn; h = hn; }

            g_h[(((size_t)d * T_ + t) * B_ + bg) * HD_ + jg] = h;
            __nv_bfloat16 hi = __float2bfloat16(h);
            __nv_bfloat16 lo = __float2bfloat16(h - __bfloat162float(hi));
            stgH[cb * 32 + cj] = hi;
            stgL[cb * 32 + cj] = lo;
        }
        px[0] = nx[0]; px[1] = nx[1]; px[2] = nx[2]; px[3] = nx[3];
        __syncthreads();

        // ---- DSMEM broadcast: warp w -> peer w ----
        if (s + 1 < maxlen) {
            int r = lane >> 2, q = lane & 3;
            uint4 hv = *(const uint4*)((const char*)stgH + r * 64 + q * 16);
            uint4 lv = *(const uint4*)((const char*)stgL + r * 64 + q * 16);
            uint32_t dh = sb + (uint32_t)(OFF_A0HI + nbuf * 8448 + r * W_STR + 32 * rank + q * 8) * 2;
            uint32_t dl = dh + 4224 * 2;
            uint32_t mb = sb + BY_MBAR + nbuf * 8;
            uint32_t rdh = mapa_rank(dh, (uint32_t)wid);
            uint32_t rdl = mapa_rank(dl, (uint32_t)wid);
            uint32_t rmb = mapa_rank(mb, (uint32_t)wid);
            STS_CL_V4(rdh, hv);
            STS_CL_V4(rdl, lv);
            MBAR_ARRIVE_REMOTE(rmb);
        }
        t += dt;
    }

    // fwd: frozen h on fully-masked tail
    if (d == 0) {
        for (int tt = maxlen; tt < T_; ++tt)
            g_h[(((size_t)0 * T_ + tt) * B_ + bg) * HD_ + jg] = h;
    }

    asm volatile("barrier.cluster.arrive.aligned;" ::: "memory");
    asm volatile("barrier.cluster.wait.aligned;"   ::: "memory");
}

// =========================================================================
// K3: W_tag transpose
// =========================================================================
__global__ void k3_wt(const float* __restrict__ W_tag)
{
    int kk = threadIdx.x;
    for (int k = 0; k < 32; ++k)
        g_Wt[kk * 32 + k] = W_tag[k * 512 + kk];
}

// =========================================================================
// K4: h_tag = [h_f,h_b] @ W_tag^T + b_tag
// =========================================================================
__global__ __launch_bounds__(256) void k4_htag(const float* __restrict__ b_tag)
{
    __shared__ float hrow[8][512];
    const int tid = threadIdx.x;
    const int r0 = blockIdx.x * 8;

    for (int u = tid; u < 1024; u += 256) {
        int rl = u >> 7;
        int off = (u & 127) * 4;
        int r = r0 + rl;
        int t = r >> 6, b = r & 63;
        const float* src = (off < 256)
            ? &g_h[(((size_t)0 * T_ + t) * B_ + b) * HD_ + off]
            : &g_h[(((size_t)1 * T_ + t) * B_ + b) * HD_ + off - 256];
        *(float4*)&hrow[rl][off] = *(const float4*)src;
    }
    __syncthreads();

    const int rl = tid >> 5;
    const int k  = tid & 31;
    float acc = b_tag[k];
#pragma unroll 8
    for (int kk = 0; kk < 512; ++kk)
        acc = fmaf(hrow[rl][kk], g_Wt[kk * 32 + k], acc);
    g_htag[(size_t)(r0 + rl) * 32 + k] = acc;
}

// =========================================================================
// K5: CRF forward + gold score (unchanged).
// =========================================================================
__global__ __launch_bounds__(32) void k5_crf(
    const int* __restrict__ mask, const int* __restrict__ gold,
    const float* __restrict__ trans, float* __restrict__ out)
{
    __shared__ unsigned mw[16];
    const int b = blockIdx.x;
    const int k = threadIdx.x;

    float trow[32];
#pragma unroll
    for (int j = 0; j < 32; ++j) trow[j] = trans[k * 32 + j];

    for (int blk = 0; blk < 16; ++blk) {
        int bit = mask[b * T_ + blk * 32 + k];
        unsigned wword = __ballot_sync(0xffffffffu, bit != 0);
        if (k == 0) mw[blk] = wword;
    }
    __syncwarp();

    float score = (k == STOP_) ? 0.f : -10000.f;
    float emit = g_htag[((size_t)0 * B_ + b) * 32 + k];

    for (int t = 0; t < T_; ++t) {
        int tn = (t + 1 < T_) ? t + 1 : t;
        float emit_n = g_htag[((size_t)tn * B_ + b) * 32 + k];
        int m = (mw[t >> 5] >> (t & 31)) & 1;

        float v[32];
#pragma unroll
        for (int j = 0; j < 32; ++j)
            v[j] = __shfl_sync(0xffffffffu, score, j) + trow[j];

        float m16[16], m8[8], m4[4], m2[2];
#pragma unroll
        for (int j = 0; j < 16; ++j) m16[j] = fmaxf(v[j], v[j + 16]);
#pragma unroll
        for (int j = 0; j < 8; ++j)  m8[j] = fmaxf(m16[j], m16[j + 8]);
#pragma unroll
        for (int j = 0; j < 4; ++j)  m4[j] = fmaxf(m8[j], m8[j + 4]);
        m2[0] = fmaxf(m4[0], m4[2]); m2[1] = fmaxf(m4[1], m4[3]);
        float mx = fmaxf(m2[0], m2[1]);

        float e[32];
#pragma unroll
        for (int j = 0; j < 32; ++j) e[j] = __expf(v[j] - mx);
        float s16[16], s8[8], s4[4], s2[2];
#pragma unroll
        for (int j = 0; j < 16; ++j) s16[j] = e[j] + e[j + 16];
#pragma unroll
        for (int j = 0; j < 8; ++j)  s8[j] = s16[j] + s16[j + 8];
#pragma unroll
        for (int j = 0; j < 4; ++j)  s4[j] = s8[j] + s8[j + 4];
        s2[0] = s4[0] + s4[2]; s2[1] = s4[1] + s4[3];
        float sum = s2[0] + s2[1];

        float sn = emit + mx + __logf(sum);
        score = m ? sn : score;
        emit = emit_n;
    }

    float zt = score + trans[STOP_ * 32 + k];
    float mx = zt;
#pragma unroll
    for (int o = 16; o; o >>= 1) mx = fmaxf(mx, __shfl_xor_sync(0xffffffffu, mx, o));
    float es = __expf(zt - mx);
#pragma unroll
    for (int o = 16; o; o >>= 1) es += __shfl_xor_sync(0xffffffffu, es, o);
    float Z = mx + __logf(es);

    float gs = 0.f;
    int len = 0;
    for (int i = k; i < T_; i += 32) {
        int m = mask[b * T_ + i];
        len += m;
        if (i < T_ - 1 && m) {
            int g1 = gold[b * T_ + i + 1];
            int g0 = gold[b * T_ + i];
            gs += g_htag[((size_t)i * B_ + b) * 32 + g1] + trans[g1 * 32 + g0];
        }
    }
#pragma unroll
    for (int o = 16; o; o >>= 1) {
        gs  += __shfl_xor_sync(0xffffffffu, gs, o);
        len += __shfl_xor_sync(0xffffffffu, len, o);
    }
    if (k == 0) {
        int last = gold[b * T_ + len - 1];
        out[b] = Z - (gs + trans[STOP_ * 32 + last]);
    }
}

// =========================================================================
extern "C" void kernel_launch(void* const* d_in, const int* in_sizes, int n_in,
                              void* d_out, int out_size)
{
    const int*   inp   = (const int*)  d_in[0];
    const int*   gold  = (const int*)  d_in[1];
    const int*   mask  = (const int*)  d_in[2];
    const float* emb   = (const float*)d_in[3];
    const float* Wih_f = (const float*)d_in[4];
    const float* Whh_f = (const float*)d_in[5];
    const float* b_f   = (const float*)d_in[6];
    const float* Wih_b = (const float*)d_in[7];
    const float* Whh_b = (const float*)d_in[8];
    const float* b_b   = (const float*)d_in[9];
    const float* W_tag = (const float*)d_in[10];
    const float* b_tag = (const float*)d_in[11];
    const float* trans = (const float*)d_in[12];
    float* out = (float*)d_out;
    (void)in_sizes; (void)n_in; (void)out_size;

    cudaFuncSetAttribute(k1_mma,  cudaFuncAttributeMaxDynamicSharedMemorySize, K1_SMEM);
    cudaFuncSetAttribute(k2_lstm, cudaFuncAttributeMaxDynamicSharedMemorySize, K2_SMEM);

    k0_conv<<<8704, 256>>>(inp, emb, Wih_f, Wih_b);
    k3_wt<<<1, 512>>>(W_tag);
    k1_mma<<<dim3(16, 256), 256, K1_SMEM>>>(b_f, b_b);
    k2_lstm<<<128, 256, K2_SMEM>>>(Whh_f, Whh_b, mask);
    k4_htag<<<(T_ * B_) / 8, 256>>>(b_tag);
    k5_crf<<<B_, 32>>>(mask, gold, trans, out);
}

// round 14
// speedup vs baseline: 3.7141x; 1.2040x over previous
#include <cuda_runtime.h>
#include <cuda_bf16.h>
#include <cstdint>
#include <cstddef>

#define T_ 512
#define B_ 64
#define HD_ 256
#define STOP_ 30

// single dynamic-smem symbol
extern __shared__ __align__(16) char dyn_smem[];

// ---------------- device scratch ----------------
__device__ float g_xw[(size_t)2 * T_ * B_ * 1024];   // [dir][t][b][4H]
__device__ float g_h[(size_t)2 * T_ * B_ * HD_];     // [dir][t][b][H]
__device__ float g_htag[(size_t)T_ * B_ * 32];
__device__ float g_Wt[512 * 32];
__device__ __nv_bfloat16 g_ahi[(size_t)32768 * 256];
__device__ __nv_bfloat16 g_alo[(size_t)32768 * 256];
__device__ __nv_bfloat16 g_bhi[(size_t)2048 * 256];
__device__ __nv_bfloat16 g_blo[(size_t)2048 * 256];

// ---------------- PTX helpers ----------------
__device__ __forceinline__ uint32_t smem_u32(const void* p) {
    uint32_t a;
    asm("{ .reg .u64 t; cvta.to.shared.u64 t, %1; cvt.u32.u64 %0, t; }" : "=r"(a) : "l"(p));
    return a;
}
#define LDSM_X4(r, addr) \
    asm volatile("ldmatrix.sync.aligned.m8n8.x4.shared.b16 {%0,%1,%2,%3}, [%4];" \
        : "=r"((r)[0]), "=r"((r)[1]), "=r"((r)[2]), "=r"((r)[3]) : "r"(addr))
#define LDSM_X2(r, addr) \
    asm volatile("ldmatrix.sync.aligned.m8n8.x2.shared.b16 {%0,%1}, [%2];" \
        : "=r"((r)[0]), "=r"((r)[1]) : "r"(addr))
__device__ __forceinline__ void mma16816(float* c, const uint32_t* a, const uint32_t* b) {
    asm volatile("mma.sync.aligned.m16n8k16.row.col.f32.bf16.bf16.f32 "
        "{%0,%1,%2,%3}, {%4,%5,%6,%7}, {%8,%9}, {%0,%1,%2,%3};"
        : "+f"(c[0]), "+f"(c[1]), "+f"(c[2]), "+f"(c[3])
        : "r"(a[0]), "r"(a[1]), "r"(a[2]), "r"(a[3]), "r"(b[0]), "r"(b[1]));
}
#define MBAR_INIT(mb, c) asm volatile("mbarrier.init.shared.b64 [%0], %1;" :: "r"(mb), "r"((uint32_t)(c)) : "memory")
__device__ __forceinline__ void mbar_wait_cl(uint32_t mb, uint32_t parity) {
    asm volatile(
        "{\n\t.reg .pred P;\n\t"
        "WL_%=:\n\t"
        "mbarrier.try_wait.parity.acquire.cluster.shared::cta.b64 P, [%0], %1, 0x989680;\n\t"
        "@P bra WD_%=;\n\t"
        "bra WL_%=;\n\t"
        "WD_%=:\n\t}"
        :: "r"(mb), "r"(parity) : "memory");
}
__device__ __forceinline__ uint32_t mapa_rank(uint32_t a, uint32_t r) {
    uint32_t o;
    asm("mapa.shared::cluster.u32 %0, %1, %2;" : "=r"(o) : "r"(a), "r"(r));
    return o;
}
#define STS_CL_V4(addr, v) \
    asm volatile("st.shared::cluster.v4.b32 [%0], {%1,%2,%3,%4};" \
        :: "r"(addr), "r"((v).x), "r"((v).y), "r"((v).z), "r"((v).w) : "memory")
#define MBAR_ARRIVE_REMOTE(addr) \
    asm volatile("mbarrier.arrive.release.cluster.shared::cluster.b64 _, [%0];" :: "r"(addr) : "memory")

// =========================================================================
// K0: gather emb rows + split-convert A and B to bf16 hi/lo. (unchanged)
// =========================================================================
__global__ __launch_bounds__(256) void k0_conv(
    const int* __restrict__ inp, const float* __restrict__ emb,
    const float* __restrict__ Wih_f, const float* __restrict__ Wih_b)
{
    size_t u = (size_t)blockIdx.x * 256 + threadIdx.x;
    const float* src;
    __nv_bfloat16 *dhi, *dlo;
    size_t off;
    if (u < 2097152) {
        int r = (int)(u >> 6);
        int q = (int)(u & 63);
        int tok = inp[(r & 63) * T_ + (r >> 6)];
        src = emb + (size_t)tok * 256 + q * 4;
        off = (size_t)r * 256 + q * 4;
        dhi = g_ahi; dlo = g_alo;
    } else {
        size_t v = u - 2097152;
        if (v >= 131072) return;
        int r = (int)(v >> 6);
        int q = (int)(v & 63);
        src = (r < 1024 ? Wih_f + (size_t)r * 256
                        : Wih_b + (size_t)(r - 1024) * 256) + q * 4;
        off = (size_t)r * 256 + q * 4;
        dhi = g_bhi; dlo = g_blo;
    }
    float4 a = *(const float4*)src;
    __nv_bfloat162 h0 = __floats2bfloat162_rn(a.x, a.y);
    __nv_bfloat162 h1 = __floats2bfloat162_rn(a.z, a.w);
    __nv_bfloat162 l0 = __floats2bfloat162_rn(a.x - __bfloat162float(h0.x),
                                              a.y - __bfloat162float(h0.y));
    __nv_bfloat162 l1 = __floats2bfloat162_rn(a.z - __bfloat162float(h1.x),
                                              a.w - __bfloat162float(h1.y));
    *(uint2*)(dhi + off) = make_uint2(*(uint32_t*)&h0, *(uint32_t*)&h1);
    *(uint2*)(dlo + off) = make_uint2(*(uint32_t*)&l0, *(uint32_t*)&l1);
}

// =========================================================================
// K1: xW = A @ B^T + bias via mma.sync bf16 split (unchanged).
// =========================================================================
#define K1_STR  72
#define K1_AHI  0
#define K1_ALO  (128 * K1_STR)
#define K1_BHI  (2 * 128 * K1_STR)
#define K1_BLO  (3 * 128 * K1_STR)
#define K1_BIAS_B (4 * 128 * K1_STR * 2)
#define K1_SMEM (K1_BIAS_B + 512 + 128)

__global__ __launch_bounds__(256, 2) void k1_mma(
    const float* __restrict__ b_f, const float* __restrict__ b_b)
{
    __nv_bfloat16* smb = (__nv_bfloat16*)dyn_smem;
    float* sbias = (float*)(dyn_smem + K1_BIAS_B);
    const uint32_t sA = smem_u32(smb);
    const int tid = threadIdx.x;
    const int wid = tid >> 5, lane = tid & 31;
    const int row0 = blockIdx.y * 128;
    const int col0 = blockIdx.x * 128;
    const int dir = col0 >> 10, gi0 = col0 & 1023;
    const int wm = wid >> 2, wn = wid & 3;

    if (tid < 128) {
        int g = col0 + tid;
        sbias[tid] = (g < 1024) ? b_f[g] : b_b[g - 1024];
    }

    float acc[4][4][4];
#pragma unroll
    for (int i = 0; i < 4; ++i)
#pragma unroll
        for (int j = 0; j < 4; ++j)
#pragma unroll
            for (int e = 0; e < 4; ++e) acc[i][j][e] = 0.f;

    for (int kc = 0; kc < 4; ++kc) {
        __syncthreads();
        {
            int r  = tid >> 1;
            int g2 = (tid & 1) * 4;
            size_t abase = (size_t)(row0 + r) * 256 + kc * 64 + g2 * 8;
            size_t bbase = (size_t)(col0 + r) * 256 + kc * 64 + g2 * 8;
            int so = r * K1_STR + g2 * 8;
#pragma unroll
            for (int i = 0; i < 4; ++i) {
                *(uint4*)(smb + K1_AHI + so + i * 8) = *(const uint4*)(g_ahi + abase + i * 8);
                *(uint4*)(smb + K1_ALO + so + i * 8) = *(const uint4*)(g_alo + abase + i * 8);
                *(uint4*)(smb + K1_BHI + so + i * 8) = *(const uint4*)(g_bhi + bbase + i * 8);
                *(uint4*)(smb + K1_BLO + so + i * 8) = *(const uint4*)(g_blo + bbase + i * 8);
            }
        }
        __syncthreads();

#pragma unroll
        for (int ks = 0; ks < 4; ++ks) {
            uint32_t bh[4][2], bl[4][2];
#pragma unroll
            for (int nf = 0; nf < 4; ++nf) {
                int nrow = wn * 32 + nf * 8 + (lane & 7);
                int kof  = ks * 16 + ((lane >> 3) & 1) * 8;
                LDSM_X2(bh[nf], sA + (uint32_t)(K1_BHI + nrow * K1_STR + kof) * 2);
                LDSM_X2(bl[nf], sA + (uint32_t)(K1_BLO + nrow * K1_STR + kof) * 2);
            }
            uint32_t af[4][4];
            {
                int mrow = wm * 64 + (lane & 15);
                int kof  = ks * 16 + (lane >> 4) * 8;
#pragma unroll
                for (int mf = 0; mf < 4; ++mf)
                    LDSM_X4(af[mf], sA + (uint32_t)(K1_AHI + (mrow + mf * 16) * K1_STR + kof) * 2);
#pragma unroll
                for (int mf = 0; mf < 4; ++mf)
#pragma unroll
                    for (int nf = 0; nf < 4; ++nf) {
                        mma16816(acc[mf][nf], af[mf], bh[nf]);
                        mma16816(acc[mf][nf], af[mf], bl[nf]);
                    }
#pragma unroll
                for (int mf = 0; mf < 4; ++mf)
                    LDSM_X4(af[mf], sA + (uint32_t)(K1_ALO + (mrow + mf * 16) * K1_STR + kof) * 2);
#pragma unroll
                for (int mf = 0; mf < 4; ++mf)
#pragma unroll
                    for (int nf = 0; nf < 4; ++nf)
                        mma16816(acc[mf][nf], af[mf], bh[nf]);
            }
        }
    }

    const int gq = lane >> 2, tq = lane & 3;
#pragma unroll
    for (int mf = 0; mf < 4; ++mf)
#pragma unroll
        for (int i2 = 0; i2 < 2; ++i2) {
            int m = wm * 64 + mf * 16 + gq + i2 * 8;
            int r = row0 + m;
            int t = r >> 6, b = r & 63;
            float* dst = g_xw + (((size_t)dir * T_ + t) * B_ + b) * 1024 + gi0;
#pragma unroll
            for (int nf = 0; nf < 4; ++nf) {
                int n = wn * 32 + nf * 8 + tq * 2;
                float2 v;
                v.x = acc[mf][nf][i2 * 2 + 0] + sbias[n];
                v.y = acc[mf][nf][i2 * 2 + 1] + sbias[n + 1];
                *(float2*)(dst + n) = v;
            }
        }
}

// =========================================================================
// K2: BiLSTM recurrence, tensor cores + DSMEM exchange, W frags in regs.
// (identical to R13 k2 — provably equivalent to the passing R12 version)
// =========================================================================
#define W_STR 264
#define OFF_WHI  0
#define OFF_WLO  33792
#define OFF_A0HI 67584
#define BY_SG    168960
#define BY_MSK   173312
#define BY_STG   177408
#define BY_MBAR  178432
#define BY_MAX   178448
#define K2_SMEM  178464

__device__ __forceinline__ float fsig(float x) { return 1.f / (1.f + __expf(-x)); }

__global__ __launch_bounds__(256, 1) __cluster_dims__(8, 1, 1)
void k2_lstm(const float* __restrict__ Whh_f, const float* __restrict__ Whh_b,
             const int* __restrict__ mask)
{
    __nv_bfloat16* SM = (__nv_bfloat16*)dyn_smem;
    float* sg  = (float*)(dyn_smem + BY_SG);    // [4 g][8 b][34]
    char*  msk = dyn_smem + BY_MSK;             // [8 b][512]
    __nv_bfloat16* stgH = (__nv_bfloat16*)(dyn_smem + BY_STG);
    __nv_bfloat16* stgL = (__nv_bfloat16*)(dyn_smem + BY_STG + 512);
    int* smax = (int*)(dyn_smem + BY_MAX);
    const uint32_t sb = smem_u32(dyn_smem);

    const int tid  = threadIdx.x;
    const int wid  = tid >> 5;
    const int lane = tid & 31;
    const int rank = blockIdx.x & 7;
    const int cid  = blockIdx.x >> 3;
    const int d    = cid >> 3;
    const int G    = cid & 7;
    const int cb = tid >> 5;
    const int cj = tid & 31;
    const int jg = 32 * rank + cj;
    const int bg = 8 * G + cb;

    if (tid == 0) {
        MBAR_INIT(sb + BY_MBAR, 256);
        MBAR_INIT(sb + BY_MBAR + 8, 256);
        *smax = 0;
    }
    {
        const float* Whh = d ? Whh_b : Whh_f;
        for (int n = wid; n < 128; n += 8) {
            const float* row = Whh + (size_t)((n >> 5) * 256 + 32 * rank + (n & 31)) * 256;
#pragma unroll
            for (int k0 = lane * 4; k0 < 256; k0 += 128) {
                float4 v = *(const float4*)(row + k0);
                __nv_bfloat162 h0 = __floats2bfloat162_rn(v.x, v.y);
                __nv_bfloat162 h1 = __floats2bfloat162_rn(v.z, v.w);
                __nv_bfloat162 l0 = __floats2bfloat162_rn(v.x - __bfloat162float(h0.x),
                                                          v.y - __bfloat162float(h0.y));
                __nv_bfloat162 l1 = __floats2bfloat162_rn(v.z - __bfloat162float(h1.x),
                                                          v.w - __bfloat162float(h1.y));
                *(uint2*)(SM + OFF_WHI + n * W_STR + k0) = make_uint2(*(uint32_t*)&h0, *(uint32_t*)&h1);
                *(uint2*)(SM + OFF_WLO + n * W_STR + k0) = make_uint2(*(uint32_t*)&l0, *(uint32_t*)&l1);
            }
        }
        __nv_bfloat16 z = __float2bfloat16(0.f);
        for (int u = tid; u < 16896; u += 256)
            SM[OFF_A0HI + u] = z;
        for (int u = tid; u < 4096; u += 256)
            msk[u] = (char)mask[(8 * G + (u >> 9)) * T_ + (u & 511)];
    }
    __syncthreads();
    {
        int part = (int)msk[tid] + (int)msk[256 + tid];
#pragma unroll
        for (int o = 16; o; o >>= 1) part += __shfl_xor_sync(0xffffffffu, part, o);
        if (lane == 0) atomicAdd(smax, part);
    }
    __syncthreads();
    const int maxlen = *smax;

    // ---- hoist W fragments (hi+lo, all 16 k-steps) into registers ----
    const int brow = wid * 16 + (lane & 7);
    const int bkof = ((lane >> 3) & 1) * 8;
    uint32_t rbh[16][4], rbl[16][4];
#pragma unroll
    for (int ks = 0; ks < 16; ++ks) {
        const int k = ks * 16;
        LDSM_X2(&rbh[ks][0], sb + (uint32_t)(OFF_WHI + brow * W_STR + k + bkof) * 2);
        LDSM_X2(&rbh[ks][2], sb + (uint32_t)(OFF_WHI + (brow + 8) * W_STR + k + bkof) * 2);
        LDSM_X2(&rbl[ks][0], sb + (uint32_t)(OFF_WLO + brow * W_STR + k + bkof) * 2);
        LDSM_X2(&rbl[ks][2], sb + (uint32_t)(OFF_WLO + (brow + 8) * W_STR + k + bkof) * 2);
    }

    asm volatile("barrier.cluster.arrive.aligned;" ::: "memory");
    asm volatile("barrier.cluster.wait.aligned;"   ::: "memory");

    const int dt = d ? -1 : 1;
    int t = d ? (maxlen - 1) : 0;

    if (d == 1) {
        for (int tt = maxlen; tt < T_; ++tt)
            g_h[(((size_t)1 * T_ + tt) * B_ + bg) * HD_ + jg] = 0.f;
    }

    float c = 0.f, h = 0.f;
    float px[4];
    {
        const float* xp = g_xw + (((size_t)d * T_ + t) * B_ + bg) * 1024 + jg;
        px[0] = xp[0]; px[1] = xp[256]; px[2] = xp[512]; px[3] = xp[768];
    }

    const int mrow = lane & 15;
    const int akof = (lane >> 4) * 8;
    const int gq = lane >> 2, tq = lane & 3;
    int ph0 = 0, ph1 = 0;

    for (int s = 0; s < maxlen; ++s) {
        const int buf  = s & 1;
        const int nbuf = buf ^ 1;
        const int a_hi = OFF_A0HI + buf * 8448;
        const int a_lo = a_hi + 4224;

        // prefetch next step's xw BEFORE the exchange wait
        float nx[4];
        {
            int tn = (s + 1 < maxlen) ? t + dt : t;
            const float* xp = g_xw + (((size_t)d * T_ + tn) * B_ + bg) * 1024 + jg;
            nx[0] = xp[0]; nx[1] = xp[256]; nx[2] = xp[512]; nx[3] = xp[768];
        }
        if (s > 0) {
            uint32_t mb = sb + BY_MBAR + buf * 8;
            if (buf) { mbar_wait_cl(mb, (uint32_t)ph1); ph1 ^= 1; }
            else     { mbar_wait_cl(mb, (uint32_t)ph0); ph0 ^= 1; }
        }

        // ---- tensor-core gate GEMM (3 passes, fp32 accum; W in regs) ----
        float acc0[4] = {0.f, 0.f, 0.f, 0.f};
        float acc1[4] = {0.f, 0.f, 0.f, 0.f};
#pragma unroll
        for (int ks = 0; ks < 16; ++ks) {
            const int k = ks * 16;
            uint32_t ah[4], al[4];
            LDSM_X4(ah, sb + (uint32_t)(a_hi + mrow * W_STR + k + akof) * 2);
            LDSM_X4(al, sb + (uint32_t)(a_lo + mrow * W_STR + k + akof) * 2);
            mma16816(acc0, ah, &rbh[ks][0]);  mma16816(acc1, ah, &rbh[ks][2]);
            mma16816(acc0, ah, &rbl[ks][0]);  mma16816(acc1, ah, &rbl[ks][2]);
            mma16816(acc0, al, &rbh[ks][0]);  mma16816(acc1, al, &rbh[ks][2]);
        }

        // ---- scatter gates (rows 0..7 real) ----
        if (gq < 8) {
            {
                int n = wid * 16 + tq * 2;
                int g = n >> 5, j = n & 31;
                sg[(g * 8 + gq) * 34 + j]     = acc0[0];
                sg[(g * 8 + gq) * 34 + j + 1] = acc0[1];
            }
            {
                int n = wid * 16 + 8 + tq * 2;
                int g = n >> 5, j = n & 31;
                sg[(g * 8 + gq) * 34 + j]     = acc1[0];
                sg[(g * 8 + gq) * 34 + j + 1] = acc1[1];
            }
        }
        __syncthreads();

        // ---- cell update (1 cell per thread) + stage h hi/lo ----
        {
            int m = msk[cb * 512 + t];
            float zi = sg[(0 * 8 + cb) * 34 + cj] + px[0];
            float zf = sg[(1 * 8 + cb) * 34 + cj] + px[1];
            float zg = sg[(2 * 8 + cb) * 34 + cj] + px[2];
            float zo = sg[(3 * 8 + cb) * 34 + cj] + px[3];
            float cn = fsig(zf) * c + fsig(zi) * tanhf(zg);
            float hn = fsig(zo) * tanhf(cn);
            if (m) { c = cn; h = hn; }

            g_h[(((size_t)d * T_ + t) * B_ + bg) * HD_ + jg] = h;
            __nv_bfloat16 hi = __float2bfloat16(h);
            __nv_bfloat16 lo = __float2bfloat16(h - __bfloat162float(hi));
            stgH[cb * 32 + cj] = hi;
            stgL[cb * 32 + cj] = lo;
        }
        px[0] = nx[0]; px[1] = nx[1]; px[2] = nx[2]; px[3] = nx[3];
        __syncthreads();

        // ---- DSMEM broadcast: warp w -> peer rank w ----
        if (s + 1 < maxlen) {
            int r = lane >> 2, q = lane & 3;
            uint4 hv = *(const uint4*)((const char*)stgH + r * 64 + q * 16);
            uint4 lv = *(const uint4*)((const char*)stgL + r * 64 + q * 16);
            uint32_t dh = sb + (uint32_t)(OFF_A0HI + nbuf * 8448 + r * W_STR + 32 * rank + q * 8) * 2;
            uint32_t dl = dh + 4224 * 2;
            uint32_t mb = sb + BY_MBAR + nbuf * 8;
            uint32_t rdh = mapa_rank(dh, (uint32_t)wid);
            uint32_t rdl = mapa_rank(dl, (uint32_t)wid);
            uint32_t rmb = mapa_rank(mb, (uint32_t)wid);
            STS_CL_V4(rdh, hv);
            STS_CL_V4(rdl, lv);
            MBAR_ARRIVE_REMOTE(rmb);
        }
        t += dt;
    }

    if (d == 0) {
        for (int tt = maxlen; tt < T_; ++tt)
            g_h[(((size_t)0 * T_ + tt) * B_ + bg) * HD_ + jg] = h;
    }

    asm volatile("barrier.cluster.arrive.aligned;" ::: "memory");
    asm volatile("barrier.cluster.wait.aligned;"   ::: "memory");
}

// =========================================================================
// K3: W_tag transpose
// =========================================================================
__global__ void k3_wt(const float* __restrict__ W_tag)
{
    int kk = threadIdx.x;
    for (int k = 0; k < 32; ++k)
        g_Wt[kk * 32 + k] = W_tag[k * 512 + kk];
}

// =========================================================================
// K4: h_tag = [h_f,h_b] @ W_tag^T + b_tag (unchanged)
// =========================================================================
__global__ __launch_bounds__(256) void k4_htag(const float* __restrict__ b_tag)
{
    __shared__ float hrow[8][512];
    const int tid = threadIdx.x;
    const int r0 = blockIdx.x * 8;

    for (int u = tid; u < 1024; u += 256) {
        int rl = u >> 7;
        int off = (u & 127) * 4;
        int r = r0 + rl;
        int t = r >> 6, b = r & 63;
        const float* src = (off < 256)
            ? &g_h[(((size_t)0 * T_ + t) * B_ + b) * HD_ + off]
            : &g_h[(((size_t)1 * T_ + t) * B_ + b) * HD_ + off - 256];
        *(float4*)&hrow[rl][off] = *(const float4*)src;
    }
    __syncthreads();

    const int rl = tid >> 5;
    const int k  = tid & 31;
    float acc = b_tag[k];
#pragma unroll 8
    for (int kk = 0; kk < 512; ++kk)
        acc = fmaf(hrow[rl][kk], g_Wt[kk * 32 + k], acc);
    g_htag[(size_t)(r0 + rl) * 32 + k] = acc;
}

// =========================================================================
// K5: CRF forward + gold score — reverted to the R12 exact per-k tree LSE
// (the passing version).
// =========================================================================
__global__ __launch_bounds__(32) void k5_crf(
    const int* __restrict__ mask, const int* __restrict__ gold,
    const float* __restrict__ trans, float* __restrict__ out)
{
    __shared__ unsigned mw[16];
    const int b = blockIdx.x;
    const int k = threadIdx.x;

    float trow[32];
#pragma unroll
    for (int j = 0; j < 32; ++j) trow[j] = trans[k * 32 + j];

    for (int blk = 0; blk < 16; ++blk) {
        int bit = mask[b * T_ + blk * 32 + k];
        unsigned wword = __ballot_sync(0xffffffffu, bit != 0);
        if (k == 0) mw[blk] = wword;
    }
    __syncwarp();

    float score = (k == STOP_) ? 0.f : -10000.f;
    float emit = g_htag[((size_t)0 * B_ + b) * 32 + k];

    for (int t = 0; t < T_; ++t) {
        int tn = (t + 1 < T_) ? t + 1 : t;
        float emit_n = g_htag[((size_t)tn * B_ + b) * 32 + k];
        int m = (mw[t >> 5] >> (t & 31)) & 1;

        float v[32];
#pragma unroll
        for (int j = 0; j < 32; ++j)
            v[j] = __shfl_sync(0xffffffffu, score, j) + trow[j];

        float m16[16], m8[8], m4[4], m2[2];
#pragma unroll
        for (int j = 0; j < 16; ++j) m16[j] = fmaxf(v[j], v[j + 16]);
#pragma unroll
        for (int j = 0; j < 8; ++j)  m8[j] = fmaxf(m16[j], m16[j + 8]);
#pragma unroll
        for (int j = 0; j < 4; ++j)  m4[j] = fmaxf(m8[j], m8[j + 4]);
        m2[0] = fmaxf(m4[0], m4[2]); m2[1] = fmaxf(m4[1], m4[3]);
        float mx = fmaxf(m2[0], m2[1]);

        float e[32];
#pragma unroll
        for (int j = 0; j < 32; ++j) e[j] = __expf(v[j] - mx);
        float s16[16], s8[8], s4[4], s2[2];
#pragma unroll
        for (int j = 0; j < 16; ++j) s16[j] = e[j] + e[j + 16];
#pragma unroll
        for (int j = 0; j < 8; ++j)  s8[j] = s16[j] + s16[j + 8];
#pragma unroll
        for (int j = 0; j < 4; ++j)  s4[j] = s8[j] + s8[j + 4];
        s2[0] = s4[0] + s4[2]; s2[1] = s4[1] + s4[3];
        float sum = s2[0] + s2[1];

        float sn = emit + mx + __logf(sum);
        score = m ? sn : score;
        emit = emit_n;
    }

    float zt = score + trans[STOP_ * 32 + k];
    float mx = zt;
#pragma unroll
    for (int o = 16; o; o >>= 1) mx = fmaxf(mx, __shfl_xor_sync(0xffffffffu, mx, o));
    float es = __expf(zt - mx);
#pragma unroll
    for (int o = 16; o; o >>= 1) es += __shfl_xor_sync(0xffffffffu, es, o);
    float Z = mx + __logf(es);

    float gs = 0.f;
    int len = 0;
    for (int i = k; i < T_; i += 32) {
        int m = mask[b * T_ + i];
        len += m;
        if (i < T_ - 1 && m) {
            int g1 = gold[b * T_ + i + 1];
            int g0 = gold[b * T_ + i];
            gs += g_htag[((size_t)i * B_ + b) * 32 + g1] + trans[g1 * 32 + g0];
        }
    }
#pragma unroll
    for (int o = 16; o; o >>= 1) {
        gs  += __shfl_xor_sync(0xffffffffu, gs, o);
        len += __shfl_xor_sync(0xffffffffu, len, o);
    }
    if (k == 0) {
        int last = gold[b * T_ + len - 1];
        out[b] = Z - (gs + trans[STOP_ * 32 + last]);
    }
}

// =========================================================================
extern "C" void kernel_launch(void* const* d_in, const int* in_sizes, int n_in,
                              void* d_out, int out_size)
{
    const int*   inp   = (const int*)  d_in[0];
    const int*   gold  = (const int*)  d_in[1];
    const int*   mask  = (const int*)  d_in[2];
    const float* emb   = (const float*)d_in[3];
    const float* Wih_f = (const float*)d_in[4];
    const float* Whh_f = (const float*)d_in[5];
    const float* b_f   = (const float*)d_in[6];
    const float* Wih_b = (const float*)d_in[7];
    const float* Whh_b = (const float*)d_in[8];
    const float* b_b   = (const float*)d_in[9];
    const float* W_tag = (const float*)d_in[10];
    const float* b_tag = (const float*)d_in[11];
    const float* trans = (const float*)d_in[12];
    float* out = (float*)d_out;
    (void)in_sizes; (void)n_in; (void)out_size;

    cudaFuncSetAttribute(k1_mma,  cudaFuncAttributeMaxDynamicSharedMemorySize, K1_SMEM);
    cudaFuncSetAttribute(k2_lstm, cudaFuncAttributeMaxDynamicSharedMemorySize, K2_SMEM);

    k0_conv<<<8704, 256>>>(inp, emb, Wih_f, Wih_b);
    k3_wt<<<1, 512>>>(W_tag);
    k1_mma<<<dim3(16, 256), 256, K1_SMEM>>>(b_f, b_b);
    k2_lstm<<<128, 256, K2_SMEM>>>(Whh_f, Whh_b, mask);
    k4_htag<<<(T_ * B_) / 8, 256>>>(b_tag);
    k5_crf<<<B_, 32>>>(mask, gold, trans, out);
}